// round 8
// baseline (speedup 1.0000x reference)
#include <cuda_runtime.h>
#include <cuda_bf16.h>
#include <math.h>

// ---------------- problem constants ----------------
#define BB   4
#define SS   1024
#define TT   4096        // B*S tokens
#define HH   1024
#define NHD  4           // heads
#define HD   256         // head dim
#define EE   8           // experts
#define KK   2           // top-k
#define VV   32000
#define LL   2
#define FF4  4096        // 4H
#define EH   2048        // 2H

// ---------------- device scratch (no allocations allowed) ----------------
__device__ float g_x[(size_t)TT * HH];            // 16 MB  activations
__device__ float g_qkv[(size_t)TT * 3 * HH];      // 48 MB
__device__ float g_scores[(size_t)BB * NHD * SS * SS]; // 64 MB
__device__ float g_ao[(size_t)TT * HH];           // 16 MB
__device__ float g_buf[(size_t)TT * HH];          // 16 MB
__device__ float g_ff[(size_t)TT * FF4];          // 64 MB
__device__ float g_h[(size_t)TT * KK * EH];       // 64 MB  (slot-indexed expert hidden)
__device__ float g_y[(size_t)TT * KK * HH];       // 32 MB  (slot-indexed expert out)
__device__ int   g_list[EE * TT];
__device__ int   g_counts[EE];

// ---------------- helpers ----------------
__device__ __forceinline__ float gelu_exact(float v) {
    return 0.5f * v * (1.0f + erff(v * 0.70710678118654752440f));
}

// ---------------- generic 128x128x8 fp32 tile GEMM body ----------------
// C[m,n] = act( alpha * sum_k A[m,k]*B(k,n) + bias[n] )
// TRANSB=false: B is KxN row-major (ldb = row stride).
// TRANSB=true : B is NxK row-major (C = A * B^T).
// amap/amode: A-row gather. amode 0: direct. 1: row = amap[r]>>1. 2: row = amap[r].
// cmap: C-row scatter (row = cmap[r]) or nullptr for direct.
#define BM 128
#define BN 128
#define BKD 8

template<bool TRANSB>
__device__ __forceinline__ void gemm_tile_body(
    const float* __restrict__ A, const float* __restrict__ B,
    const float* __restrict__ bias, float* __restrict__ C,
    int M, int N, int K, int lda, int ldb, int ldc,
    float alpha, int act,
    const int* __restrict__ amap, int amode, const int* __restrict__ cmap)
{
    __shared__ float As[BKD][BM];
    __shared__ float Bs[BKD][BN];

    const int tid  = threadIdx.x;
    const int row0 = blockIdx.y * BM;
    const int col0 = blockIdx.x * BN;

    // A load mapping: each thread loads one float4 along k
    const int a_m = tid >> 1;           // 0..127
    const int a_k = (tid & 1) * 4;      // 0 or 4
    const int r_load = row0 + a_m;
    const bool a_ok = (r_load < M);
    long a_off = 0;
    if (a_ok) {
        int rr = r_load;
        if (amode == 1)      rr = amap[r_load] >> 1;
        else if (amode == 2) rr = amap[r_load];
        a_off = (long)rr * lda;
    }

    float acc[8][8];
#pragma unroll
    for (int i = 0; i < 8; i++)
#pragma unroll
        for (int j = 0; j < 8; j++) acc[i][j] = 0.f;

    const int ty = tid >> 4;   // 0..15
    const int tx = tid & 15;   // 0..15

    for (int k0 = 0; k0 < K; k0 += BKD) {
        float4 av = make_float4(0.f, 0.f, 0.f, 0.f);
        if (a_ok) av = *(const float4*)(A + a_off + k0 + a_k);
        As[a_k + 0][a_m] = av.x;
        As[a_k + 1][a_m] = av.y;
        As[a_k + 2][a_m] = av.z;
        As[a_k + 3][a_m] = av.w;

        if (!TRANSB) {
            const int bk = tid >> 5;            // 0..7
            const int bn = (tid & 31) * 4;      // 0..124
            float4 bv = *(const float4*)(B + (long)(k0 + bk) * ldb + col0 + bn);
            *(float4*)&Bs[bk][bn] = bv;
        } else {
            const int bn = tid >> 1;            // 0..127
            const int bk = (tid & 1) * 4;       // 0 or 4
            float4 bv = *(const float4*)(B + (long)(col0 + bn) * ldb + k0 + bk);
            Bs[bk + 0][bn] = bv.x;
            Bs[bk + 1][bn] = bv.y;
            Bs[bk + 2][bn] = bv.z;
            Bs[bk + 3][bn] = bv.w;
        }
        __syncthreads();

#pragma unroll
        for (int kk = 0; kk < BKD; kk++) {
            float ra[8], rb[8];
            *(float4*)(ra)     = *(const float4*)&As[kk][ty * 8];
            *(float4*)(ra + 4) = *(const float4*)&As[kk][ty * 8 + 4];
            *(float4*)(rb)     = *(const float4*)&Bs[kk][tx * 8];
            *(float4*)(rb + 4) = *(const float4*)&Bs[kk][tx * 8 + 4];
#pragma unroll
            for (int i = 0; i < 8; i++)
#pragma unroll
                for (int j = 0; j < 8; j++)
                    acc[i][j] += ra[i] * rb[j];
        }
        __syncthreads();
    }

#pragma unroll
    for (int i = 0; i < 8; i++) {
        const int ri = row0 + ty * 8 + i;
        if (ri >= M) continue;
        const long c_off = (long)(cmap ? cmap[ri] : ri) * ldc;
#pragma unroll
        for (int j = 0; j < 8; j += 4) {
            const int c = col0 + tx * 8 + j;
            float4 o;
            o.x = acc[i][j + 0] * alpha + (bias ? bias[c + 0] : 0.f);
            o.y = acc[i][j + 1] * alpha + (bias ? bias[c + 1] : 0.f);
            o.z = acc[i][j + 2] * alpha + (bias ? bias[c + 2] : 0.f);
            o.w = acc[i][j + 3] * alpha + (bias ? bias[c + 3] : 0.f);
            if (act == 1) {
                o.x = fmaxf(o.x, 0.f); o.y = fmaxf(o.y, 0.f);
                o.z = fmaxf(o.z, 0.f); o.w = fmaxf(o.w, 0.f);
            } else if (act == 2) {
                o.x = gelu_exact(o.x); o.y = gelu_exact(o.y);
                o.z = gelu_exact(o.z); o.w = gelu_exact(o.w);
            }
            *(float4*)(C + c_off + c) = o;
        }
    }
}

// ---------------- kernels ----------------
template<bool TRANSB>
__global__ void __launch_bounds__(256) k_gemm(
    const float* __restrict__ A, const float* __restrict__ B,
    const float* __restrict__ bias, float* __restrict__ C,
    int M, int N, int K, int lda, int ldb, int ldc, float alpha, int act)
{
    gemm_tile_body<TRANSB>(A, B, bias, C, M, N, K, lda, ldb, ldc, alpha, act,
                           nullptr, 0, nullptr);
}

__global__ void __launch_bounds__(256) k_embed(const int* __restrict__ ids,
                                               const float* __restrict__ emb,
                                               float* __restrict__ x)
{
    long i = (long)blockIdx.x * 256 + threadIdx.x;   // < TT*HH
    int t = (int)(i >> 10);
    int h = (int)(i & 1023);
    x[i] = emb[(long)ids[t] * HH + h];
}

// scores[z, q, k] = (1/16) * sum_d Q[b,q,h,d] * K[b,k,h,d]
__global__ void __launch_bounds__(256) k_attn_scores()
{
    const int z = blockIdx.z;           // b*NHD + h
    const int b = z >> 2, h = z & 3;
    const float* A  = g_qkv + (long)b * SS * (3 * HH) + h * HD;          // Q
    const float* Bp = A + HH;                                            // K
    float* C = g_scores + (long)z * SS * SS;
    gemm_tile_body<true>(A, Bp, nullptr, C, SS, SS, HD, 3 * HH, 3 * HH, SS,
                         0.0625f, 0, nullptr, 0, nullptr);
}

// ao[b,q,h,d] = sum_k P[z,q,k] * V[b,k,h,d]
__global__ void __launch_bounds__(256) k_attn_av()
{
    const int z = blockIdx.z;
    const int b = z >> 2, h = z & 3;
    const float* A  = g_scores + (long)z * SS * SS;
    const float* Bp = g_qkv + (long)b * SS * (3 * HH) + 2 * HH + h * HD; // V
    float* C = g_ao + (long)b * SS * HH + h * HD;
    gemm_tile_body<false>(A, Bp, nullptr, C, SS, HD, SS, SS, 3 * HH, HH,
                          1.0f, 0, nullptr, 0, nullptr);
}

__global__ void __launch_bounds__(256) k_softmax(float* __restrict__ data, int ncols)
{
    float* row = data + (long)blockIdx.x * ncols;
    const int tid = threadIdx.x;
    __shared__ float red[256];

    float m = -3.4e38f;
    for (int j = tid; j < ncols; j += 256) m = fmaxf(m, row[j]);
    red[tid] = m; __syncthreads();
    for (int o = 128; o > 0; o >>= 1) {
        if (tid < o) red[tid] = fmaxf(red[tid], red[tid + o]);
        __syncthreads();
    }
    m = red[0];
    __syncthreads();

    float s = 0.f;
    for (int j = tid; j < ncols; j += 256) {
        float e = expf(row[j] - m);
        row[j] = e;
        s += e;
    }
    red[tid] = s; __syncthreads();
    for (int o = 128; o > 0; o >>= 1) {
        if (tid < o) red[tid] += red[tid + o];
        __syncthreads();
    }
    const float inv = 1.f / red[0];
    for (int j = tid; j < ncols; j += 256) row[j] *= inv;
}

// x[t] = LayerNorm(x[t] + res[t]) * g + b   (in place on x)
__global__ void __launch_bounds__(256) k_add_ln(float* __restrict__ x,
                                                const float* __restrict__ res,
                                                const float* __restrict__ g,
                                                const float* __restrict__ b)
{
    const int t = blockIdx.x;
    const int tid = threadIdx.x;
    const long base = (long)t * HH;
    __shared__ float red[256];

    float v[4];
    float s = 0.f;
#pragma unroll
    for (int i = 0; i < 4; i++) {
        v[i] = x[base + tid + i * 256] + res[base + tid + i * 256];
        s += v[i];
    }
    red[tid] = s; __syncthreads();
    for (int o = 128; o > 0; o >>= 1) {
        if (tid < o) red[tid] += red[tid + o];
        __syncthreads();
    }
    const float mean = red[0] * (1.0f / HH);
    __syncthreads();

    float s2 = 0.f;
#pragma unroll
    for (int i = 0; i < 4; i++) {
        float d = v[i] - mean;
        s2 += d * d;
    }
    red[tid] = s2; __syncthreads();
    for (int o = 128; o > 0; o >>= 1) {
        if (tid < o) red[tid] += red[tid + o];
        __syncthreads();
    }
    const float inv = rsqrtf(red[0] * (1.0f / HH) + 1e-5f);
#pragma unroll
    for (int i = 0; i < 4; i++) {
        int c = tid + i * 256;
        x[base + c] = (v[i] - mean) * inv * g[c] + b[c];
    }
}

__global__ void k_zero_counts()
{
    if (threadIdx.x < EE) g_counts[threadIdx.x] = 0;
}

// gate logits + top-2 routing (one block / token, 8 warps = 8 experts)
__global__ void __launch_bounds__(256) k_gate(const float* __restrict__ x,
                                              const float* __restrict__ gw,
                                              const float* __restrict__ gb)
{
    const int t = blockIdx.x;
    const int tid = threadIdx.x;
    const int w = tid >> 5, lane = tid & 31;
    const float* xr = x + (long)t * HH;

    float s = 0.f;
    for (int j = lane; j < HH; j += 32) s += xr[j] * gw[(long)j * EE + w];
#pragma unroll
    for (int o = 16; o > 0; o >>= 1) s += __shfl_down_sync(0xFFFFFFFFu, s, o);

    __shared__ float lg[EE];
    if (lane == 0) lg[w] = s + gb[w];
    __syncthreads();

    if (tid == 0) {
        int i1 = 0;
        for (int e = 1; e < EE; e++) if (lg[e] > lg[i1]) i1 = e;
        int i2 = -1;
        for (int e = 0; e < EE; e++) {
            if (e == i1) continue;
            if (i2 < 0 || lg[e] > lg[i2]) i2 = e;
        }
        int p1 = atomicAdd(&g_counts[i1], 1);
        g_list[i1 * TT + p1] = t * 2 + 0;
        int p2 = atomicAdd(&g_counts[i2], 1);
        g_list[i2 * TT + p2] = t * 2 + 1;
    }
}

// expert GEMM1: h[slot] = relu(x[token] @ W1_e + b1_e)
__global__ void __launch_bounds__(256) k_moe1(const float* __restrict__ x,
                                              const float* __restrict__ w1,
                                              const float* __restrict__ b1)
{
    const int e = blockIdx.z;
    const int cnt = g_counts[e];
    if ((int)blockIdx.y * BM >= cnt) return;
    gemm_tile_body<false>(x, w1 + (long)e * HH * EH, b1 + (long)e * EH, g_h,
                          cnt, EH, HH, HH, EH, EH, 1.0f, 1,
                          g_list + e * TT, 1, g_list + e * TT);
}

// expert GEMM2: y[slot] = h[slot] @ W2_e + b2_e
__global__ void __launch_bounds__(256) k_moe2(const float* __restrict__ w2,
                                              const float* __restrict__ b2)
{
    const int e = blockIdx.z;
    const int cnt = g_counts[e];
    if ((int)blockIdx.y * BM >= cnt) return;
    gemm_tile_body<false>(g_h, w2 + (long)e * EH * HH, b2 + (long)e * HH, g_y,
                          cnt, HH, EH, EH, HH, HH, 1.0f, 0,
                          g_list + e * TT, 2, g_list + e * TT);
}

// x[t] = y[slot 2t] + y[slot 2t+1]   (MoE replaces x, no residual per reference)
__global__ void __launch_bounds__(256) k_combine(float* __restrict__ x)
{
    long i = (long)blockIdx.x * 256 + threadIdx.x;
    int t = (int)(i >> 10);
    int h = (int)(i & 1023);
    x[i] = g_y[((long)t * 2) * HH + h] + g_y[((long)t * 2 + 1) * HH + h];
}

// ---------------- host launcher ----------------
extern "C" void kernel_launch(void* const* d_in, const int* in_sizes, int n_in,
                              void* d_out, int out_size)
{
    (void)in_sizes; (void)n_in; (void)out_size;

    const int*   ids    = (const int*)d_in[0];
    const float* embed  = (const float*)d_in[1];
    const float* qkv_w  = (const float*)d_in[2];
    const float* qkv_b  = (const float*)d_in[3];
    const float* out_w  = (const float*)d_in[4];
    const float* out_b  = (const float*)d_in[5];
    const float* ln1g   = (const float*)d_in[6];
    const float* ln1b   = (const float*)d_in[7];
    const float* ffw1   = (const float*)d_in[8];
    const float* ffb1   = (const float*)d_in[9];
    const float* ffw2   = (const float*)d_in[10];
    const float* ffb2   = (const float*)d_in[11];
    const float* ln2g   = (const float*)d_in[12];
    const float* ln2b   = (const float*)d_in[13];
    const float* gw     = (const float*)d_in[14];
    const float* gb     = (const float*)d_in[15];
    const float* ew1    = (const float*)d_in[16];
    const float* eb1    = (const float*)d_in[17];
    const float* ew2    = (const float*)d_in[18];
    const float* eb2    = (const float*)d_in[19];
    const float* lmw    = (const float*)d_in[20];
    const float* lmb    = (const float*)d_in[21];
    float* out = (float*)d_out;

    float *p_x, *p_qkv, *p_ao, *p_buf, *p_ff, *p_scores;
    cudaGetSymbolAddress((void**)&p_x,      g_x);
    cudaGetSymbolAddress((void**)&p_qkv,    g_qkv);
    cudaGetSymbolAddress((void**)&p_ao,     g_ao);
    cudaGetSymbolAddress((void**)&p_buf,    g_buf);
    cudaGetSymbolAddress((void**)&p_ff,     g_ff);
    cudaGetSymbolAddress((void**)&p_scores, g_scores);

    // ---- embedding ----
    k_embed<<<(TT * HH) / 256, 256>>>(ids, embed, p_x);

    for (int l = 0; l < LL; l++) {
        // QKV: x @ W^T + b    [T,3H]
        k_gemm<true><<<dim3(3 * HH / BN, TT / BM), 256>>>(
            p_x, qkv_w + (long)l * 3 * HH * HH, qkv_b + (long)l * 3 * HH, p_qkv,
            TT, 3 * HH, HH, HH, HH, 3 * HH, 1.0f, 0);

        // attention
        k_attn_scores<<<dim3(SS / BN, SS / BM, BB * NHD), 256>>>();
        k_softmax<<<BB * NHD * SS, 256>>>(p_scores, SS);
        k_attn_av<<<dim3(HD / BN, SS / BM, BB * NHD), 256>>>();

        // out proj: ao @ Wo^T + b
        k_gemm<true><<<dim3(HH / BN, TT / BM), 256>>>(
            p_ao, out_w + (long)l * HH * HH, out_b + (long)l * HH, p_buf,
            TT, HH, HH, HH, HH, HH, 1.0f, 0);

        // x = LN(x + attn_out)
        k_add_ln<<<TT, 256>>>(p_x, p_buf, ln1g + (long)l * HH, ln1b + (long)l * HH);

        // FFN
        k_gemm<false><<<dim3(FF4 / BN, TT / BM), 256>>>(
            p_x, ffw1 + (long)l * HH * FF4, ffb1 + (long)l * FF4, p_ff,
            TT, FF4, HH, HH, FF4, FF4, 1.0f, 2 /*gelu*/);
        k_gemm<false><<<dim3(HH / BN, TT / BM), 256>>>(
            p_ff, ffw2 + (long)l * FF4 * HH, ffb2 + (long)l * HH, p_buf,
            TT, HH, FF4, FF4, HH, HH, 1.0f, 0);

        // x = LN(x + ff)
        k_add_ln<<<TT, 256>>>(p_x, p_buf, ln2g + (long)l * HH, ln2b + (long)l * HH);

        // MoE: route top-2, compute only selected experts
        k_zero_counts<<<1, 32>>>();
        k_gate<<<TT, 256>>>(p_x, gw + (long)l * HH * EE, gb + (long)l * EE);
        k_moe1<<<dim3(EH / BN, TT / BM, EE), 256>>>(
            p_x, ew1 + (long)l * EE * HH * EH, eb1 + (long)l * EE * EH);
        k_moe2<<<dim3(HH / BN, TT / BM, EE), 256>>>(
            ew2 + (long)l * EE * EH * HH, eb2 + (long)l * EE * HH);
        k_combine<<<(TT * HH) / 256, 256>>>(p_x);
    }

    // ---- lm head: x @ W + b  -> [T, V] ----
    k_gemm<false><<<dim3(VV / BN, TT / BM), 256>>>(
        p_x, lmw, lmb, out, TT, VV, HH, HH, VV, VV, 1.0f, 0);
}

// round 9
// speedup vs baseline: 1.0019x; 1.0019x over previous
#include <cuda_runtime.h>
#include <cuda_bf16.h>
#include <math.h>

// ---------------- problem constants ----------------
#define BB   4
#define SS   1024
#define TT   4096        // B*S tokens
#define HH   1024
#define NHD  4           // heads
#define HD   256         // head dim
#define EE   8           // experts
#define KK   2           // top-k
#define VV   32000
#define LL   2
#define FF4  4096        // 4H
#define EH   2048        // 2H

// ---------------- device scratch (no allocations allowed) ----------------
__device__ float g_x[(size_t)TT * HH];            // 16 MB  activations
__device__ float g_qkv[(size_t)TT * 3 * HH];      // 48 MB
__device__ float g_scores[(size_t)BB * NHD * SS * SS]; // 64 MB
__device__ float g_ao[(size_t)TT * HH];           // 16 MB
__device__ float g_buf[(size_t)TT * HH];          // 16 MB
__device__ float g_ff[(size_t)TT * FF4];          // 64 MB
__device__ float g_h[(size_t)TT * KK * EH];       // 64 MB  (slot-indexed expert hidden)
__device__ float g_y[(size_t)TT * KK * HH];       // 32 MB  (slot-indexed expert out)
__device__ int   g_list[EE * TT];
__device__ int   g_counts[EE];

// ---------------- helpers ----------------
__device__ __forceinline__ float gelu_exact(float v) {
    return 0.5f * v * (1.0f + erff(v * 0.70710678118654752440f));
}

// ---------------- generic 128x128x8 fp32 tile GEMM body ----------------
// C[m,n] = act( alpha * sum_k A[m,k]*B(k,n) + bias[n] )
// TRANSB=false: B is KxN row-major (ldb = row stride).
// TRANSB=true : B is NxK row-major (C = A * B^T).
// amap/amode: A-row gather. amode 0: direct. 1: row = amap[r]>>1. 2: row = amap[r].
// cmap: C-row scatter (row = cmap[r]) or nullptr for direct.
#define BM 128
#define BN 128
#define BKD 8

template<bool TRANSB>
__device__ __forceinline__ void gemm_tile_body(
    const float* __restrict__ A, const float* __restrict__ B,
    const float* __restrict__ bias, float* __restrict__ C,
    int M, int N, int K, int lda, int ldb, int ldc,
    float alpha, int act,
    const int* __restrict__ amap, int amode, const int* __restrict__ cmap)
{
    __shared__ float As[BKD][BM];
    __shared__ float Bs[BKD][BN];

    const int tid  = threadIdx.x;
    const int row0 = blockIdx.y * BM;
    const int col0 = blockIdx.x * BN;

    // A load mapping: each thread loads one float4 along k
    const int a_m = tid >> 1;           // 0..127
    const int a_k = (tid & 1) * 4;      // 0 or 4
    const int r_load = row0 + a_m;
    const bool a_ok = (r_load < M);
    long a_off = 0;
    if (a_ok) {
        int rr = r_load;
        if (amode == 1)      rr = amap[r_load] >> 1;
        else if (amode == 2) rr = amap[r_load];
        a_off = (long)rr * lda;
    }

    float acc[8][8];
#pragma unroll
    for (int i = 0; i < 8; i++)
#pragma unroll
        for (int j = 0; j < 8; j++) acc[i][j] = 0.f;

    const int ty = tid >> 4;   // 0..15
    const int tx = tid & 15;   // 0..15

    for (int k0 = 0; k0 < K; k0 += BKD) {
        float4 av = make_float4(0.f, 0.f, 0.f, 0.f);
        if (a_ok) av = *(const float4*)(A + a_off + k0 + a_k);
        As[a_k + 0][a_m] = av.x;
        As[a_k + 1][a_m] = av.y;
        As[a_k + 2][a_m] = av.z;
        As[a_k + 3][a_m] = av.w;

        if (!TRANSB) {
            const int bk = tid >> 5;            // 0..7
            const int bn = (tid & 31) * 4;      // 0..124
            float4 bv = *(const float4*)(B + (long)(k0 + bk) * ldb + col0 + bn);
            *(float4*)&Bs[bk][bn] = bv;
        } else {
            const int bn = tid >> 1;            // 0..127
            const int bk = (tid & 1) * 4;       // 0 or 4
            float4 bv = *(const float4*)(B + (long)(col0 + bn) * ldb + k0 + bk);
            Bs[bk + 0][bn] = bv.x;
            Bs[bk + 1][bn] = bv.y;
            Bs[bk + 2][bn] = bv.z;
            Bs[bk + 3][bn] = bv.w;
        }
        __syncthreads();

#pragma unroll
        for (int kk = 0; kk < BKD; kk++) {
            float ra[8], rb[8];
            *(float4*)(ra)     = *(const float4*)&As[kk][ty * 8];
            *(float4*)(ra + 4) = *(const float4*)&As[kk][ty * 8 + 4];
            *(float4*)(rb)     = *(const float4*)&Bs[kk][tx * 8];
            *(float4*)(rb + 4) = *(const float4*)&Bs[kk][tx * 8 + 4];
#pragma unroll
            for (int i = 0; i < 8; i++)
#pragma unroll
                for (int j = 0; j < 8; j++)
                    acc[i][j] += ra[i] * rb[j];
        }
        __syncthreads();
    }

#pragma unroll
    for (int i = 0; i < 8; i++) {
        const int ri = row0 + ty * 8 + i;
        if (ri >= M) continue;
        const long c_off = (long)(cmap ? cmap[ri] : ri) * ldc;
#pragma unroll
        for (int j = 0; j < 8; j += 4) {
            const int c = col0 + tx * 8 + j;
            float4 o;
            o.x = acc[i][j + 0] * alpha + (bias ? bias[c + 0] : 0.f);
            o.y = acc[i][j + 1] * alpha + (bias ? bias[c + 1] : 0.f);
            o.z = acc[i][j + 2] * alpha + (bias ? bias[c + 2] : 0.f);
            o.w = acc[i][j + 3] * alpha + (bias ? bias[c + 3] : 0.f);
            if (act == 1) {
                o.x = fmaxf(o.x, 0.f); o.y = fmaxf(o.y, 0.f);
                o.z = fmaxf(o.z, 0.f); o.w = fmaxf(o.w, 0.f);
            } else if (act == 2) {
                o.x = gelu_exact(o.x); o.y = gelu_exact(o.y);
                o.z = gelu_exact(o.z); o.w = gelu_exact(o.w);
            }
            *(float4*)(C + c_off + c) = o;
        }
    }
}

// ---------------- kernels ----------------
template<bool TRANSB>
__global__ void __launch_bounds__(256) k_gemm(
    const float* __restrict__ A, const float* __restrict__ B,
    const float* __restrict__ bias, float* __restrict__ C,
    int M, int N, int K, int lda, int ldb, int ldc, float alpha, int act)
{
    gemm_tile_body<TRANSB>(A, B, bias, C, M, N, K, lda, ldb, ldc, alpha, act,
                           nullptr, 0, nullptr);
}

__global__ void __launch_bounds__(256) k_embed(const int* __restrict__ ids,
                                               const float* __restrict__ emb,
                                               float* __restrict__ x)
{
    long i = (long)blockIdx.x * 256 + threadIdx.x;   // < TT*HH
    int t = (int)(i >> 10);
    int h = (int)(i & 1023);
    x[i] = emb[(long)ids[t] * HH + h];
}

// scores[z, q, k] = (1/16) * sum_d Q[b,q,h,d] * K[b,k,h,d]
__global__ void __launch_bounds__(256) k_attn_scores()
{
    const int z = blockIdx.z;           // b*NHD + h
    const int b = z >> 2, h = z & 3;
    const float* A  = g_qkv + (long)b * SS * (3 * HH) + h * HD;          // Q
    const float* Bp = A + HH;                                            // K
    float* C = g_scores + (long)z * SS * SS;
    gemm_tile_body<true>(A, Bp, nullptr, C, SS, SS, HD, 3 * HH, 3 * HH, SS,
                         0.0625f, 0, nullptr, 0, nullptr);
}

// ao[b,q,h,d] = sum_k P[z,q,k] * V[b,k,h,d]
__global__ void __launch_bounds__(256) k_attn_av()
{
    const int z = blockIdx.z;
    const int b = z >> 2, h = z & 3;
    const float* A  = g_scores + (long)z * SS * SS;
    const float* Bp = g_qkv + (long)b * SS * (3 * HH) + 2 * HH + h * HD; // V
    float* C = g_ao + (long)b * SS * HH + h * HD;
    gemm_tile_body<false>(A, Bp, nullptr, C, SS, HD, SS, SS, 3 * HH, HH,
                          1.0f, 0, nullptr, 0, nullptr);
}

__global__ void __launch_bounds__(256) k_softmax(float* __restrict__ data, int ncols)
{
    float* row = data + (long)blockIdx.x * ncols;
    const int tid = threadIdx.x;
    __shared__ float red[256];

    float m = -3.4e38f;
    for (int j = tid; j < ncols; j += 256) m = fmaxf(m, row[j]);
    red[tid] = m; __syncthreads();
    for (int o = 128; o > 0; o >>= 1) {
        if (tid < o) red[tid] = fmaxf(red[tid], red[tid + o]);
        __syncthreads();
    }
    m = red[0];
    __syncthreads();

    float s = 0.f;
    for (int j = tid; j < ncols; j += 256) {
        float e = expf(row[j] - m);
        row[j] = e;
        s += e;
    }
    red[tid] = s; __syncthreads();
    for (int o = 128; o > 0; o >>= 1) {
        if (tid < o) red[tid] += red[tid + o];
        __syncthreads();
    }
    const float inv = 1.f / red[0];
    for (int j = tid; j < ncols; j += 256) row[j] *= inv;
}

// x[t] = LayerNorm(x[t] + res[t]) * g + b   (in place on x)
__global__ void __launch_bounds__(256) k_add_ln(float* __restrict__ x,
                                                const float* __restrict__ res,
                                                const float* __restrict__ g,
                                                const float* __restrict__ b)
{
    const int t = blockIdx.x;
    const int tid = threadIdx.x;
    const long base = (long)t * HH;
    __shared__ float red[256];

    float v[4];
    float s = 0.f;
#pragma unroll
    for (int i = 0; i < 4; i++) {
        v[i] = x[base + tid + i * 256] + res[base + tid + i * 256];
        s += v[i];
    }
    red[tid] = s; __syncthreads();
    for (int o = 128; o > 0; o >>= 1) {
        if (tid < o) red[tid] += red[tid + o];
        __syncthreads();
    }
    const float mean = red[0] * (1.0f / HH);
    __syncthreads();

    float s2 = 0.f;
#pragma unroll
    for (int i = 0; i < 4; i++) {
        float d = v[i] - mean;
        s2 += d * d;
    }
    red[tid] = s2; __syncthreads();
    for (int o = 128; o > 0; o >>= 1) {
        if (tid < o) red[tid] += red[tid + o];
        __syncthreads();
    }
    const float inv = rsqrtf(red[0] * (1.0f / HH) + 1e-5f);
#pragma unroll
    for (int i = 0; i < 4; i++) {
        int c = tid + i * 256;
        x[base + c] = (v[i] - mean) * inv * g[c] + b[c];
    }
}

__global__ void k_zero_counts()
{
    if (threadIdx.x < EE) g_counts[threadIdx.x] = 0;
}

// gate logits + top-2 routing (one block / token, 8 warps = 8 experts)
__global__ void __launch_bounds__(256) k_gate(const float* __restrict__ x,
                                              const float* __restrict__ gw,
                                              const float* __restrict__ gb)
{
    const int t = blockIdx.x;
    const int tid = threadIdx.x;
    const int w = tid >> 5, lane = tid & 31;
    const float* xr = x + (long)t * HH;

    float s = 0.f;
    for (int j = lane; j < HH; j += 32) s += xr[j] * gw[(long)j * EE + w];
#pragma unroll
    for (int o = 16; o > 0; o >>= 1) s += __shfl_down_sync(0xFFFFFFFFu, s, o);

    __shared__ float lg[EE];
    if (lane == 0) lg[w] = s + gb[w];
    __syncthreads();

    if (tid == 0) {
        int i1 = 0;
        for (int e = 1; e < EE; e++) if (lg[e] > lg[i1]) i1 = e;
        int i2 = -1;
        for (int e = 0; e < EE; e++) {
            if (e == i1) continue;
            if (i2 < 0 || lg[e] > lg[i2]) i2 = e;
        }
        int p1 = atomicAdd(&g_counts[i1], 1);
        g_list[i1 * TT + p1] = t * 2 + 0;
        int p2 = atomicAdd(&g_counts[i2], 1);
        g_list[i2 * TT + p2] = t * 2 + 1;
    }
}

// expert GEMM1: h[slot] = relu(x[token] @ W1_e + b1_e)
__global__ void __launch_bounds__(256) k_moe1(const float* __restrict__ x,
                                              const float* __restrict__ w1,
                                              const float* __restrict__ b1)
{
    const int e = blockIdx.z;
    const int cnt = g_counts[e];
    if ((int)blockIdx.y * BM >= cnt) return;
    gemm_tile_body<false>(x, w1 + (long)e * HH * EH, b1 + (long)e * EH, g_h,
                          cnt, EH, HH, HH, EH, EH, 1.0f, 1,
                          g_list + e * TT, 1, g_list + e * TT);
}

// expert GEMM2: y[slot] = h[slot] @ W2_e + b2_e
__global__ void __launch_bounds__(256) k_moe2(const float* __restrict__ w2,
                                              const float* __restrict__ b2)
{
    const int e = blockIdx.z;
    const int cnt = g_counts[e];
    if ((int)blockIdx.y * BM >= cnt) return;
    gemm_tile_body<false>(g_h, w2 + (long)e * EH * HH, b2 + (long)e * HH, g_y,
                          cnt, HH, EH, EH, HH, HH, 1.0f, 0,
                          g_list + e * TT, 2, g_list + e * TT);
}

// x[t] = y[slot 2t] + y[slot 2t+1]   (MoE replaces x, no residual per reference)
__global__ void __launch_bounds__(256) k_combine(float* __restrict__ x)
{
    long i = (long)blockIdx.x * 256 + threadIdx.x;
    int t = (int)(i >> 10);
    int h = (int)(i & 1023);
    x[i] = g_y[((long)t * 2) * HH + h] + g_y[((long)t * 2 + 1) * HH + h];
}

// ---------------- host launcher ----------------
extern "C" void kernel_launch(void* const* d_in, const int* in_sizes, int n_in,
                              void* d_out, int out_size)
{
    (void)in_sizes; (void)n_in; (void)out_size;

    const int*   ids    = (const int*)d_in[0];
    const float* embed  = (const float*)d_in[1];
    const float* qkv_w  = (const float*)d_in[2];
    const float* qkv_b  = (const float*)d_in[3];
    const float* out_w  = (const float*)d_in[4];
    const float* out_b  = (const float*)d_in[5];
    const float* ln1g   = (const float*)d_in[6];
    const float* ln1b   = (const float*)d_in[7];
    const float* ffw1   = (const float*)d_in[8];
    const float* ffb1   = (const float*)d_in[9];
    const float* ffw2   = (const float*)d_in[10];
    const float* ffb2   = (const float*)d_in[11];
    const float* ln2g   = (const float*)d_in[12];
    const float* ln2b   = (const float*)d_in[13];
    const float* gw     = (const float*)d_in[14];
    const float* gb     = (const float*)d_in[15];
    const float* ew1    = (const float*)d_in[16];
    const float* eb1    = (const float*)d_in[17];
    const float* ew2    = (const float*)d_in[18];
    const float* eb2    = (const float*)d_in[19];
    const float* lmw    = (const float*)d_in[20];
    const float* lmb    = (const float*)d_in[21];
    float* out = (float*)d_out;

    float *p_x, *p_qkv, *p_ao, *p_buf, *p_ff, *p_scores;
    cudaGetSymbolAddress((void**)&p_x,      g_x);
    cudaGetSymbolAddress((void**)&p_qkv,    g_qkv);
    cudaGetSymbolAddress((void**)&p_ao,     g_ao);
    cudaGetSymbolAddress((void**)&p_buf,    g_buf);
    cudaGetSymbolAddress((void**)&p_ff,     g_ff);
    cudaGetSymbolAddress((void**)&p_scores, g_scores);

    // ---- embedding ----
    k_embed<<<(TT * HH) / 256, 256>>>(ids, embed, p_x);

    for (int l = 0; l < LL; l++) {
        // QKV: x @ W^T + b    [T,3H]
        k_gemm<true><<<dim3(3 * HH / BN, TT / BM), 256>>>(
            p_x, qkv_w + (long)l * 3 * HH * HH, qkv_b + (long)l * 3 * HH, p_qkv,
            TT, 3 * HH, HH, HH, HH, 3 * HH, 1.0f, 0);

        // attention
        k_attn_scores<<<dim3(SS / BN, SS / BM, BB * NHD), 256>>>();
        k_softmax<<<BB * NHD * SS, 256>>>(p_scores, SS);
        k_attn_av<<<dim3(HD / BN, SS / BM, BB * NHD), 256>>>();

        // out proj: ao @ Wo^T + b
        k_gemm<true><<<dim3(HH / BN, TT / BM), 256>>>(
            p_ao, out_w + (long)l * HH * HH, out_b + (long)l * HH, p_buf,
            TT, HH, HH, HH, HH, HH, 1.0f, 0);

        // x = LN(x + attn_out)
        k_add_ln<<<TT, 256>>>(p_x, p_buf, ln1g + (long)l * HH, ln1b + (long)l * HH);

        // FFN
        k_gemm<false><<<dim3(FF4 / BN, TT / BM), 256>>>(
            p_x, ffw1 + (long)l * HH * FF4, ffb1 + (long)l * FF4, p_ff,
            TT, FF4, HH, HH, FF4, FF4, 1.0f, 2 /*gelu*/);
        k_gemm<false><<<dim3(HH / BN, TT / BM), 256>>>(
            p_ff, ffw2 + (long)l * FF4 * HH, ffb2 + (long)l * HH, p_buf,
            TT, HH, FF4, FF4, HH, HH, 1.0f, 0);

        // x = LN(x + ff)
        k_add_ln<<<TT, 256>>>(p_x, p_buf, ln2g + (long)l * HH, ln2b + (long)l * HH);

        // MoE: route top-2, compute only selected experts
        k_zero_counts<<<1, 32>>>();
        k_gate<<<TT, 256>>>(p_x, gw + (long)l * HH * EE, gb + (long)l * EE);
        k_moe1<<<dim3(EH / BN, TT / BM, EE), 256>>>(
            p_x, ew1 + (long)l * EE * HH * EH, eb1 + (long)l * EE * EH);
        k_moe2<<<dim3(HH / BN, TT / BM, EE), 256>>>(
            ew2 + (long)l * EE * EH * HH, eb2 + (long)l * EE * HH);
        k_combine<<<(TT * HH) / 256, 256>>>(p_x);
    }

    // ---- lm head: x @ W + b  -> [T, V] ----
    k_gemm<false><<<dim3(VV / BN, TT / BM), 256>>>(
        p_x, lmw, lmb, out, TT, VV, HH, HH, VV, VV, 1.0f, 0);
}

// round 10
// speedup vs baseline: 1.0025x; 1.0006x over previous
#include <cuda_runtime.h>
#include <cuda_bf16.h>
#include <math.h>

// ---------------- problem constants ----------------
#define BB   4
#define SS   1024
#define TT   4096        // B*S tokens
#define HH   1024
#define NHD  4           // heads
#define HD   256         // head dim
#define EE   8           // experts
#define KK   2           // top-k
#define VV   32000
#define LL   2
#define FF4  4096        // 4H
#define EH   2048        // 2H

// ---------------- device scratch (no allocations allowed) ----------------
__device__ float g_x[(size_t)TT * HH];            // 16 MB  activations
__device__ float g_qkv[(size_t)TT * 3 * HH];      // 48 MB
__device__ float g_scores[(size_t)BB * NHD * SS * SS]; // 64 MB
__device__ float g_ao[(size_t)TT * HH];           // 16 MB
__device__ float g_buf[(size_t)TT * HH];          // 16 MB
__device__ float g_ff[(size_t)TT * FF4];          // 64 MB
__device__ float g_h[(size_t)TT * KK * EH];       // 64 MB  (slot-indexed expert hidden)
__device__ float g_y[(size_t)TT * KK * HH];       // 32 MB  (slot-indexed expert out)
__device__ int   g_list[EE * TT];
__device__ int   g_counts[EE];

// ---------------- helpers ----------------
__device__ __forceinline__ float gelu_exact(float v) {
    return 0.5f * v * (1.0f + erff(v * 0.70710678118654752440f));
}

// ---------------- generic 128x128x8 fp32 tile GEMM body ----------------
// C[m,n] = act( alpha * sum_k A[m,k]*B(k,n) + bias[n] )
// TRANSB=false: B is KxN row-major (ldb = row stride).
// TRANSB=true : B is NxK row-major (C = A * B^T).
// amap/amode: A-row gather. amode 0: direct. 1: row = amap[r]>>1. 2: row = amap[r].
// cmap: C-row scatter (row = cmap[r]) or nullptr for direct.
#define BM 128
#define BN 128
#define BKD 8

template<bool TRANSB>
__device__ __forceinline__ void gemm_tile_body(
    const float* __restrict__ A, const float* __restrict__ B,
    const float* __restrict__ bias, float* __restrict__ C,
    int M, int N, int K, int lda, int ldb, int ldc,
    float alpha, int act,
    const int* __restrict__ amap, int amode, const int* __restrict__ cmap)
{
    __shared__ float As[BKD][BM];
    __shared__ float Bs[BKD][BN];

    const int tid  = threadIdx.x;
    const int row0 = blockIdx.y * BM;
    const int col0 = blockIdx.x * BN;

    // A load mapping: each thread loads one float4 along k
    const int a_m = tid >> 1;           // 0..127
    const int a_k = (tid & 1) * 4;      // 0 or 4
    const int r_load = row0 + a_m;
    const bool a_ok = (r_load < M);
    long a_off = 0;
    if (a_ok) {
        int rr = r_load;
        if (amode == 1)      rr = amap[r_load] >> 1;
        else if (amode == 2) rr = amap[r_load];
        a_off = (long)rr * lda;
    }

    float acc[8][8];
#pragma unroll
    for (int i = 0; i < 8; i++)
#pragma unroll
        for (int j = 0; j < 8; j++) acc[i][j] = 0.f;

    const int ty = tid >> 4;   // 0..15
    const int tx = tid & 15;   // 0..15

    for (int k0 = 0; k0 < K; k0 += BKD) {
        float4 av = make_float4(0.f, 0.f, 0.f, 0.f);
        if (a_ok) av = *(const float4*)(A + a_off + k0 + a_k);
        As[a_k + 0][a_m] = av.x;
        As[a_k + 1][a_m] = av.y;
        As[a_k + 2][a_m] = av.z;
        As[a_k + 3][a_m] = av.w;

        if (!TRANSB) {
            const int bk = tid >> 5;            // 0..7
            const int bn = (tid & 31) * 4;      // 0..124
            float4 bv = *(const float4*)(B + (long)(k0 + bk) * ldb + col0 + bn);
            *(float4*)&Bs[bk][bn] = bv;
        } else {
            const int bn = tid >> 1;            // 0..127
            const int bk = (tid & 1) * 4;       // 0 or 4
            float4 bv = *(const float4*)(B + (long)(col0 + bn) * ldb + k0 + bk);
            Bs[bk + 0][bn] = bv.x;
            Bs[bk + 1][bn] = bv.y;
            Bs[bk + 2][bn] = bv.z;
            Bs[bk + 3][bn] = bv.w;
        }
        __syncthreads();

#pragma unroll
        for (int kk = 0; kk < BKD; kk++) {
            float ra[8], rb[8];
            *(float4*)(ra)     = *(const float4*)&As[kk][ty * 8];
            *(float4*)(ra + 4) = *(const float4*)&As[kk][ty * 8 + 4];
            *(float4*)(rb)     = *(const float4*)&Bs[kk][tx * 8];
            *(float4*)(rb + 4) = *(const float4*)&Bs[kk][tx * 8 + 4];
#pragma unroll
            for (int i = 0; i < 8; i++)
#pragma unroll
                for (int j = 0; j < 8; j++)
                    acc[i][j] += ra[i] * rb[j];
        }
        __syncthreads();
    }

#pragma unroll
    for (int i = 0; i < 8; i++) {
        const int ri = row0 + ty * 8 + i;
        if (ri >= M) continue;
        const long c_off = (long)(cmap ? cmap[ri] : ri) * ldc;
#pragma unroll
        for (int j = 0; j < 8; j += 4) {
            const int c = col0 + tx * 8 + j;
            float4 o;
            o.x = acc[i][j + 0] * alpha + (bias ? bias[c + 0] : 0.f);
            o.y = acc[i][j + 1] * alpha + (bias ? bias[c + 1] : 0.f);
            o.z = acc[i][j + 2] * alpha + (bias ? bias[c + 2] : 0.f);
            o.w = acc[i][j + 3] * alpha + (bias ? bias[c + 3] : 0.f);
            if (act == 1) {
                o.x = fmaxf(o.x, 0.f); o.y = fmaxf(o.y, 0.f);
                o.z = fmaxf(o.z, 0.f); o.w = fmaxf(o.w, 0.f);
            } else if (act == 2) {
                o.x = gelu_exact(o.x); o.y = gelu_exact(o.y);
                o.z = gelu_exact(o.z); o.w = gelu_exact(o.w);
            }
            *(float4*)(C + c_off + c) = o;
        }
    }
}

// ---------------- kernels ----------------
template<bool TRANSB>
__global__ void __launch_bounds__(256) k_gemm(
    const float* __restrict__ A, const float* __restrict__ B,
    const float* __restrict__ bias, float* __restrict__ C,
    int M, int N, int K, int lda, int ldb, int ldc, float alpha, int act)
{
    gemm_tile_body<TRANSB>(A, B, bias, C, M, N, K, lda, ldb, ldc, alpha, act,
                           nullptr, 0, nullptr);
}

__global__ void __launch_bounds__(256) k_embed(const int* __restrict__ ids,
                                               const float* __restrict__ emb,
                                               float* __restrict__ x)
{
    long i = (long)blockIdx.x * 256 + threadIdx.x;   // < TT*HH
    int t = (int)(i >> 10);
    int h = (int)(i & 1023);
    x[i] = emb[(long)ids[t] * HH + h];
}

// scores[z, q, k] = (1/16) * sum_d Q[b,q,h,d] * K[b,k,h,d]
__global__ void __launch_bounds__(256) k_attn_scores()
{
    const int z = blockIdx.z;           // b*NHD + h
    const int b = z >> 2, h = z & 3;
    const float* A  = g_qkv + (long)b * SS * (3 * HH) + h * HD;          // Q
    const float* Bp = A + HH;                                            // K
    float* C = g_scores + (long)z * SS * SS;
    gemm_tile_body<true>(A, Bp, nullptr, C, SS, SS, HD, 3 * HH, 3 * HH, SS,
                         0.0625f, 0, nullptr, 0, nullptr);
}

// ao[b,q,h,d] = sum_k P[z,q,k] * V[b,k,h,d]
__global__ void __launch_bounds__(256) k_attn_av()
{
    const int z = blockIdx.z;
    const int b = z >> 2, h = z & 3;
    const float* A  = g_scores + (long)z * SS * SS;
    const float* Bp = g_qkv + (long)b * SS * (3 * HH) + 2 * HH + h * HD; // V
    float* C = g_ao + (long)b * SS * HH + h * HD;
    gemm_tile_body<false>(A, Bp, nullptr, C, SS, HD, SS, SS, 3 * HH, HH,
                          1.0f, 0, nullptr, 0, nullptr);
}

__global__ void __launch_bounds__(256) k_softmax(float* __restrict__ data, int ncols)
{
    float* row = data + (long)blockIdx.x * ncols;
    const int tid = threadIdx.x;
    __shared__ float red[256];

    float m = -3.4e38f;
    for (int j = tid; j < ncols; j += 256) m = fmaxf(m, row[j]);
    red[tid] = m; __syncthreads();
    for (int o = 128; o > 0; o >>= 1) {
        if (tid < o) red[tid] = fmaxf(red[tid], red[tid + o]);
        __syncthreads();
    }
    m = red[0];
    __syncthreads();

    float s = 0.f;
    for (int j = tid; j < ncols; j += 256) {
        float e = expf(row[j] - m);
        row[j] = e;
        s += e;
    }
    red[tid] = s; __syncthreads();
    for (int o = 128; o > 0; o >>= 1) {
        if (tid < o) red[tid] += red[tid + o];
        __syncthreads();
    }
    const float inv = 1.f / red[0];
    for (int j = tid; j < ncols; j += 256) row[j] *= inv;
}

// x[t] = LayerNorm(x[t] + res[t]) * g + b   (in place on x)
__global__ void __launch_bounds__(256) k_add_ln(float* __restrict__ x,
                                                const float* __restrict__ res,
                                                const float* __restrict__ g,
                                                const float* __restrict__ b)
{
    const int t = blockIdx.x;
    const int tid = threadIdx.x;
    const long base = (long)t * HH;
    __shared__ float red[256];

    float v[4];
    float s = 0.f;
#pragma unroll
    for (int i = 0; i < 4; i++) {
        v[i] = x[base + tid + i * 256] + res[base + tid + i * 256];
        s += v[i];
    }
    red[tid] = s; __syncthreads();
    for (int o = 128; o > 0; o >>= 1) {
        if (tid < o) red[tid] += red[tid + o];
        __syncthreads();
    }
    const float mean = red[0] * (1.0f / HH);
    __syncthreads();

    float s2 = 0.f;
#pragma unroll
    for (int i = 0; i < 4; i++) {
        float d = v[i] - mean;
        s2 += d * d;
    }
    red[tid] = s2; __syncthreads();
    for (int o = 128; o > 0; o >>= 1) {
        if (tid < o) red[tid] += red[tid + o];
        __syncthreads();
    }
    const float inv = rsqrtf(red[0] * (1.0f / HH) + 1e-5f);
#pragma unroll
    for (int i = 0; i < 4; i++) {
        int c = tid + i * 256;
        x[base + c] = (v[i] - mean) * inv * g[c] + b[c];
    }
}

__global__ void k_zero_counts()
{
    if (threadIdx.x < EE) g_counts[threadIdx.x] = 0;
}

// gate logits + top-2 routing (one block / token, 8 warps = 8 experts)
__global__ void __launch_bounds__(256) k_gate(const float* __restrict__ x,
                                              const float* __restrict__ gw,
                                              const float* __restrict__ gb)
{
    const int t = blockIdx.x;
    const int tid = threadIdx.x;
    const int w = tid >> 5, lane = tid & 31;
    const float* xr = x + (long)t * HH;

    float s = 0.f;
    for (int j = lane; j < HH; j += 32) s += xr[j] * gw[(long)j * EE + w];
#pragma unroll
    for (int o = 16; o > 0; o >>= 1) s += __shfl_down_sync(0xFFFFFFFFu, s, o);

    __shared__ float lg[EE];
    if (lane == 0) lg[w] = s + gb[w];
    __syncthreads();

    if (tid == 0) {
        int i1 = 0;
        for (int e = 1; e < EE; e++) if (lg[e] > lg[i1]) i1 = e;
        int i2 = -1;
        for (int e = 0; e < EE; e++) {
            if (e == i1) continue;
            if (i2 < 0 || lg[e] > lg[i2]) i2 = e;
        }
        int p1 = atomicAdd(&g_counts[i1], 1);
        g_list[i1 * TT + p1] = t * 2 + 0;
        int p2 = atomicAdd(&g_counts[i2], 1);
        g_list[i2 * TT + p2] = t * 2 + 1;
    }
}

// expert GEMM1: h[slot] = relu(x[token] @ W1_e + b1_e)
__global__ void __launch_bounds__(256) k_moe1(const float* __restrict__ x,
                                              const float* __restrict__ w1,
                                              const float* __restrict__ b1)
{
    const int e = blockIdx.z;
    const int cnt = g_counts[e];
    if ((int)blockIdx.y * BM >= cnt) return;
    gemm_tile_body<false>(x, w1 + (long)e * HH * EH, b1 + (long)e * EH, g_h,
                          cnt, EH, HH, HH, EH, EH, 1.0f, 1,
                          g_list + e * TT, 1, g_list + e * TT);
}

// expert GEMM2: y[slot] = h[slot] @ W2_e + b2_e
__global__ void __launch_bounds__(256) k_moe2(const float* __restrict__ w2,
                                              const float* __restrict__ b2)
{
    const int e = blockIdx.z;
    const int cnt = g_counts[e];
    if ((int)blockIdx.y * BM >= cnt) return;
    gemm_tile_body<false>(g_h, w2 + (long)e * EH * HH, b2 + (long)e * HH, g_y,
                          cnt, HH, EH, EH, HH, HH, 1.0f, 0,
                          g_list + e * TT, 2, g_list + e * TT);
}

// x[t] = y[slot 2t] + y[slot 2t+1]   (MoE replaces x, no residual per reference)
__global__ void __launch_bounds__(256) k_combine(float* __restrict__ x)
{
    long i = (long)blockIdx.x * 256 + threadIdx.x;
    int t = (int)(i >> 10);
    int h = (int)(i & 1023);
    x[i] = g_y[((long)t * 2) * HH + h] + g_y[((long)t * 2 + 1) * HH + h];
}

// ---------------- host launcher ----------------
extern "C" void kernel_launch(void* const* d_in, const int* in_sizes, int n_in,
                              void* d_out, int out_size)
{
    (void)in_sizes; (void)n_in; (void)out_size;

    const int*   ids    = (const int*)d_in[0];
    const float* embed  = (const float*)d_in[1];
    const float* qkv_w  = (const float*)d_in[2];
    const float* qkv_b  = (const float*)d_in[3];
    const float* out_w  = (const float*)d_in[4];
    const float* out_b  = (const float*)d_in[5];
    const float* ln1g   = (const float*)d_in[6];
    const float* ln1b   = (const float*)d_in[7];
    const float* ffw1   = (const float*)d_in[8];
    const float* ffb1   = (const float*)d_in[9];
    const float* ffw2   = (const float*)d_in[10];
    const float* ffb2   = (const float*)d_in[11];
    const float* ln2g   = (const float*)d_in[12];
    const float* ln2b   = (const float*)d_in[13];
    const float* gw     = (const float*)d_in[14];
    const float* gb     = (const float*)d_in[15];
    const float* ew1    = (const float*)d_in[16];
    const float* eb1    = (const float*)d_in[17];
    const float* ew2    = (const float*)d_in[18];
    const float* eb2    = (const float*)d_in[19];
    const float* lmw    = (const float*)d_in[20];
    const float* lmb    = (const float*)d_in[21];
    float* out = (float*)d_out;

    float *p_x, *p_qkv, *p_ao, *p_buf, *p_ff, *p_scores;
    cudaGetSymbolAddress((void**)&p_x,      g_x);
    cudaGetSymbolAddress((void**)&p_qkv,    g_qkv);
    cudaGetSymbolAddress((void**)&p_ao,     g_ao);
    cudaGetSymbolAddress((void**)&p_buf,    g_buf);
    cudaGetSymbolAddress((void**)&p_ff,     g_ff);
    cudaGetSymbolAddress((void**)&p_scores, g_scores);

    // ---- embedding ----
    k_embed<<<(TT * HH) / 256, 256>>>(ids, embed, p_x);

    for (int l = 0; l < LL; l++) {
        // QKV: x @ W^T + b    [T,3H]
        k_gemm<true><<<dim3(3 * HH / BN, TT / BM), 256>>>(
            p_x, qkv_w + (long)l * 3 * HH * HH, qkv_b + (long)l * 3 * HH, p_qkv,
            TT, 3 * HH, HH, HH, HH, 3 * HH, 1.0f, 0);

        // attention
        k_attn_scores<<<dim3(SS / BN, SS / BM, BB * NHD), 256>>>();
        k_softmax<<<BB * NHD * SS, 256>>>(p_scores, SS);
        k_attn_av<<<dim3(HD / BN, SS / BM, BB * NHD), 256>>>();

        // out proj: ao @ Wo^T + b
        k_gemm<true><<<dim3(HH / BN, TT / BM), 256>>>(
            p_ao, out_w + (long)l * HH * HH, out_b + (long)l * HH, p_buf,
            TT, HH, HH, HH, HH, HH, 1.0f, 0);

        // x = LN(x + attn_out)
        k_add_ln<<<TT, 256>>>(p_x, p_buf, ln1g + (long)l * HH, ln1b + (long)l * HH);

        // FFN
        k_gemm<false><<<dim3(FF4 / BN, TT / BM), 256>>>(
            p_x, ffw1 + (long)l * HH * FF4, ffb1 + (long)l * FF4, p_ff,
            TT, FF4, HH, HH, FF4, FF4, 1.0f, 2 /*gelu*/);
        k_gemm<false><<<dim3(HH / BN, TT / BM), 256>>>(
            p_ff, ffw2 + (long)l * FF4 * HH, ffb2 + (long)l * HH, p_buf,
            TT, HH, FF4, FF4, HH, HH, 1.0f, 0);

        // x = LN(x + ff)
        k_add_ln<<<TT, 256>>>(p_x, p_buf, ln2g + (long)l * HH, ln2b + (long)l * HH);

        // MoE: route top-2, compute only selected experts
        k_zero_counts<<<1, 32>>>();
        k_gate<<<TT, 256>>>(p_x, gw + (long)l * HH * EE, gb + (long)l * EE);
        k_moe1<<<dim3(EH / BN, TT / BM, EE), 256>>>(
            p_x, ew1 + (long)l * EE * HH * EH, eb1 + (long)l * EE * EH);
        k_moe2<<<dim3(HH / BN, TT / BM, EE), 256>>>(
            ew2 + (long)l * EE * EH * HH, eb2 + (long)l * EE * HH);
        k_combine<<<(TT * HH) / 256, 256>>>(p_x);
    }

    // ---- lm head: x @ W + b  -> [T, V] ----
    k_gemm<false><<<dim3(VV / BN, TT / BM), 256>>>(
        p_x, lmw, lmb, out, TT, VV, HH, HH, VV, VV, 1.0f, 0);
}

// round 13
// speedup vs baseline: 1.2451x; 1.2419x over previous
#include <cuda_runtime.h>
#include <cuda_bf16.h>
#include <math.h>
#include <stdint.h>

// ---------------- problem constants ----------------
#define BB   4
#define SS   1024
#define TT   4096        // B*S tokens
#define HH   1024
#define NHD  4           // heads
#define HD   256         // head dim
#define EE   8           // experts
#define KK   2           // top-k
#define VV   32000
#define LL   2
#define FF4  4096        // 4H
#define EH   2048        // 2H

// ---------------- device scratch (no allocations allowed) ----------------
__device__ float g_x[(size_t)TT * HH];
__device__ float g_qkv[(size_t)TT * 3 * HH];
__device__ float g_scores[(size_t)BB * NHD * SS * SS];
__device__ float g_ao[(size_t)TT * HH];
__device__ float g_buf[(size_t)TT * HH];
__device__ float g_ff[(size_t)TT * FF4];
__device__ float g_h[(size_t)TT * KK * EH];
__device__ float g_y[(size_t)TT * KK * HH];
__device__ int   g_list[EE * TT];
__device__ int   g_counts[EE];

// ---------------- helpers ----------------
__device__ __forceinline__ float gelu_exact(float v) {
    return 0.5f * v * (1.0f + erff(v * 0.70710678118654752440f));
}

__device__ __forceinline__ uint32_t f2tf(float f) {
    uint32_t u;
    asm("cvt.rna.tf32.f32 %0, %1;" : "=r"(u) : "f"(f));
    return u;
}

__device__ __forceinline__ void mma_tf32(float* d, const uint32_t* a, const uint32_t* b) {
    asm volatile(
        "mma.sync.aligned.m16n8k8.row.col.f32.tf32.tf32.f32 "
        "{%0,%1,%2,%3}, {%4,%5,%6,%7}, {%8,%9}, {%0,%1,%2,%3};"
        : "+f"(d[0]), "+f"(d[1]), "+f"(d[2]), "+f"(d[3])
        : "r"(a[0]), "r"(a[1]), "r"(a[2]), "r"(a[3]), "r"(b[0]), "r"(b[1]));
}

// ---------------- TF32 tensor-core 128x128x16 GEMM ----------------
// C[m,n] = act( alpha * sum_k A[m,k]*B(k,n) + bias[n] )
// NPASS=3: split-precision 3xTF32 (hi*hi + hi*lo + lo*hi) -> ~fp32 accuracy.
// NPASS=1: plain TF32 (rel err ~4e-4) -- only safe for post-routing outputs.
// TRANSB=false: B is KxN row-major.  TRANSB=true: B is NxK row-major (C=A*B^T).
// amap/amode: A-row gather (0: direct, 1: amap[r]>>1, 2: amap[r]).
// cmap: C-row scatter or nullptr.
// Requirements: K % 16 == 0, N % 128 == 0, all row strides % 4 == 0.
#define BM 128
#define BN 128
#define BKT 16
#define LDK 20   // padded k-stride in smem words (conflict-free fragment reads)

template<bool TRANSB, int NPASS>
__device__ __forceinline__ void gemm_tc_body(
    const float* __restrict__ A, const float* __restrict__ B,
    const float* __restrict__ bias, float* __restrict__ C,
    int M, int N, int K, int lda, int ldb, int ldc,
    float alpha, int act,
    const int* __restrict__ amap, int amode, const int* __restrict__ cmap)
{
    __shared__ __align__(16) float As[2][BM * LDK];
    __shared__ __align__(16) float Bs[2][BN * LDK];

    const int tid  = threadIdx.x;
    const int lane = tid & 31;
    const int warp = tid >> 5;
    const int wm   = warp >> 1;       // 0..3 (32 rows each)
    const int wn   = warp & 1;        // 0..1 (64 cols each)
    const int gid  = lane >> 2;       // 0..7
    const int ctg  = lane & 3;        // 0..3
    const int row0 = blockIdx.y * BM;
    const int col0 = blockIdx.x * BN;

    // ---- A global-load mapping: 2 x float4 per thread ----
    int  a_m[2], a_k[2];
    long a_base[2];
    bool a_ok[2];
#pragma unroll
    for (int i = 0; i < 2; i++) {
        int lin = tid + i * 256;          // 0..511
        a_m[i] = lin >> 2;                // 0..127
        a_k[i] = (lin & 3) * 4;           // 0,4,8,12
        int r = row0 + a_m[i];
        a_ok[i] = (r < M);
        long rr = r;
        if (a_ok[i]) {
            if (amode == 1)      rr = amap[r] >> 1;
            else if (amode == 2) rr = amap[r];
        }
        a_base[i] = rr * (long)lda + a_k[i];
    }

    // ---- B global-load mapping ----
    int  b_i0[2], b_i1[2];
    long b_base[2];
#pragma unroll
    for (int i = 0; i < 2; i++) {
        int lin = tid + i * 256;
        if (TRANSB) {
            b_i0[i] = lin >> 2;                        // n: 0..127
            b_i1[i] = (lin & 3) * 4;                   // k: 0,4,8,12
            b_base[i] = (long)(col0 + b_i0[i]) * ldb + b_i1[i];
        } else {
            b_i0[i] = lin >> 5;                        // k: 0..15
            b_i1[i] = (lin & 31) * 4;                  // n: 0..124
            b_base[i] = (long)b_i0[i] * ldb + col0 + b_i1[i];
        }
    }

    float acc[2][8][4];
#pragma unroll
    for (int mt = 0; mt < 2; mt++)
#pragma unroll
        for (int nt = 0; nt < 8; nt++)
#pragma unroll
            for (int q = 0; q < 4; q++) acc[mt][nt][q] = 0.f;

    float4 ar[2], br[2];

    auto ldg = [&](int k0) {
#pragma unroll
        for (int i = 0; i < 2; i++) {
            ar[i] = a_ok[i] ? *(const float4*)(A + a_base[i] + k0)
                            : make_float4(0.f, 0.f, 0.f, 0.f);
            br[i] = *(const float4*)(B + b_base[i] + (TRANSB ? (long)k0 : (long)k0 * ldb));
        }
    };

    auto sts = [&](int buf) {
#pragma unroll
        for (int i = 0; i < 2; i++) {
            float* as = &As[buf][a_m[i] * LDK + a_k[i]];
            as[0] = ar[i].x; as[1] = ar[i].y; as[2] = ar[i].z; as[3] = ar[i].w;
            if (TRANSB) {
                float* bs = &Bs[buf][b_i0[i] * LDK + b_i1[i]];
                bs[0] = br[i].x; bs[1] = br[i].y; bs[2] = br[i].z; bs[3] = br[i].w;
            } else {
                int k = b_i0[i], n = b_i1[i];
                Bs[buf][(n + 0) * LDK + k] = br[i].x;
                Bs[buf][(n + 1) * LDK + k] = br[i].y;
                Bs[buf][(n + 2) * LDK + k] = br[i].z;
                Bs[buf][(n + 3) * LDK + k] = br[i].w;
            }
        }
    };

    const int nk = K / BKT;
    ldg(0);
    sts(0);
    __syncthreads();

    int buf = 0;
    for (int kt = 0; kt < nk; kt++) {
        if (kt + 1 < nk) ldg((kt + 1) * BKT);

#pragma unroll
        for (int kh = 0; kh < 2; kh++) {
            // A fragments: hi + lo split (lo only when NPASS==3)
            uint32_t afh[2][4], afl[2][4];
#pragma unroll
            for (int mt = 0; mt < 2; mt++) {
                int r = wm * 32 + mt * 16 + gid;
                const float* a0 = &As[buf][r * LDK + kh * 8 + ctg];
                const float* a1 = &As[buf][(r + 8) * LDK + kh * 8 + ctg];
                float v[4] = { a0[0], a1[0], a0[4], a1[4] };
#pragma unroll
                for (int q = 0; q < 4; q++) {
                    afh[mt][q] = f2tf(v[q]);
                    if (NPASS == 3)
                        afl[mt][q] = f2tf(v[q] - __uint_as_float(afh[mt][q]));
                }
            }
#pragma unroll
            for (int nt = 0; nt < 8; nt++) {
                int c = wn * 64 + nt * 8 + gid;
                const float* bp = &Bs[buf][c * LDK + kh * 8 + ctg];
                float v0 = bp[0], v1 = bp[4];
                uint32_t bfh[2] = { f2tf(v0), f2tf(v1) };
                mma_tf32(acc[0][nt], afh[0], bfh);
                mma_tf32(acc[1][nt], afh[1], bfh);
                if (NPASS == 3) {
                    uint32_t bfl[2] = { f2tf(v0 - __uint_as_float(bfh[0])),
                                        f2tf(v1 - __uint_as_float(bfh[1])) };
                    mma_tf32(acc[0][nt], afh[0], bfl);
                    mma_tf32(acc[1][nt], afh[1], bfl);
                    mma_tf32(acc[0][nt], afl[0], bfh);
                    mma_tf32(acc[1][nt], afl[1], bfh);
                }
            }
        }

        if (kt + 1 < nk) sts(buf ^ 1);
        __syncthreads();
        buf ^= 1;
    }

    // ---- epilogue ----
#pragma unroll
    for (int mt = 0; mt < 2; mt++) {
#pragma unroll
        for (int half = 0; half < 2; half++) {
            int r = row0 + wm * 32 + mt * 16 + gid + half * 8;
            if (r >= M) continue;
            long co = (long)(cmap ? cmap[r] : r) * (long)ldc;
#pragma unroll
            for (int nt = 0; nt < 8; nt++) {
                int c = col0 + wn * 64 + nt * 8 + ctg * 2;
                float v0 = acc[mt][nt][half * 2 + 0] * alpha;
                float v1 = acc[mt][nt][half * 2 + 1] * alpha;
                if (bias) { v0 += bias[c]; v1 += bias[c + 1]; }
                if (act == 1) {
                    v0 = fmaxf(v0, 0.f); v1 = fmaxf(v1, 0.f);
                } else if (act == 2) {
                    v0 = gelu_exact(v0); v1 = gelu_exact(v1);
                }
                *(float2*)(C + co + c) = make_float2(v0, v1);
            }
        }
    }
}

// ---------------- kernels ----------------
template<bool TRANSB, int NPASS>
__global__ void __launch_bounds__(256) k_gemm(
    const float* __restrict__ A, const float* __restrict__ B,
    const float* __restrict__ bias, float* __restrict__ C,
    int M, int N, int K, int lda, int ldb, int ldc, float alpha, int act)
{
    gemm_tc_body<TRANSB, NPASS>(A, B, bias, C, M, N, K, lda, ldb, ldc, alpha, act,
                                nullptr, 0, nullptr);
}

__global__ void __launch_bounds__(256) k_embed(const int* __restrict__ ids,
                                               const float* __restrict__ emb,
                                               float* __restrict__ x)
{
    long i = (long)blockIdx.x * 256 + threadIdx.x;
    int t = (int)(i >> 10);
    int h = (int)(i & 1023);
    x[i] = emb[(long)ids[t] * HH + h];
}

// scores[z,q,k] = (1/16) * Q . K
__global__ void __launch_bounds__(256) k_attn_scores()
{
    const int z = blockIdx.z;
    const int b = z >> 2, h = z & 3;
    const float* A  = g_qkv + (long)b * SS * (3 * HH) + h * HD;  // Q
    const float* Bp = A + HH;                                    // K
    float* C = g_scores + (long)z * SS * SS;
    gemm_tc_body<true, 3>(A, Bp, nullptr, C, SS, SS, HD, 3 * HH, 3 * HH, SS,
                          0.0625f, 0, nullptr, 0, nullptr);
}

// ao[b,q,h,d] = P @ V
__global__ void __launch_bounds__(256) k_attn_av()
{
    const int z = blockIdx.z;
    const int b = z >> 2, h = z & 3;
    const float* A  = g_scores + (long)z * SS * SS;
    const float* Bp = g_qkv + (long)b * SS * (3 * HH) + 2 * HH + h * HD;
    float* C = g_ao + (long)b * SS * HH + h * HD;
    gemm_tc_body<false, 3>(A, Bp, nullptr, C, SS, HD, SS, SS, 3 * HH, HH,
                           1.0f, 0, nullptr, 0, nullptr);
}

__global__ void __launch_bounds__(256) k_softmax(float* __restrict__ data, int ncols)
{
    float* row = data + (long)blockIdx.x * ncols;
    const int tid = threadIdx.x;
    __shared__ float red[256];

    float m = -3.4e38f;
    for (int j = tid; j < ncols; j += 256) m = fmaxf(m, row[j]);
    red[tid] = m; __syncthreads();
    for (int o = 128; o > 0; o >>= 1) {
        if (tid < o) red[tid] = fmaxf(red[tid], red[tid + o]);
        __syncthreads();
    }
    m = red[0];
    __syncthreads();

    float s = 0.f;
    for (int j = tid; j < ncols; j += 256) {
        float e = expf(row[j] - m);
        row[j] = e;
        s += e;
    }
    red[tid] = s; __syncthreads();
    for (int o = 128; o > 0; o >>= 1) {
        if (tid < o) red[tid] += red[tid + o];
        __syncthreads();
    }
    const float inv = 1.f / red[0];
    for (int j = tid; j < ncols; j += 256) row[j] *= inv;
}

__global__ void __launch_bounds__(256) k_add_ln(float* __restrict__ x,
                                                const float* __restrict__ res,
                                                const float* __restrict__ g,
                                                const float* __restrict__ b)
{
    const int t = blockIdx.x;
    const int tid = threadIdx.x;
    const long base = (long)t * HH;
    __shared__ float red[256];

    float v[4];
    float s = 0.f;
#pragma unroll
    for (int i = 0; i < 4; i++) {
        v[i] = x[base + tid + i * 256] + res[base + tid + i * 256];
        s += v[i];
    }
    red[tid] = s; __syncthreads();
    for (int o = 128; o > 0; o >>= 1) {
        if (tid < o) red[tid] += red[tid + o];
        __syncthreads();
    }
    const float mean = red[0] * (1.0f / HH);
    __syncthreads();

    float s2 = 0.f;
#pragma unroll
    for (int i = 0; i < 4; i++) {
        float d = v[i] - mean;
        s2 += d * d;
    }
    red[tid] = s2; __syncthreads();
    for (int o = 128; o > 0; o >>= 1) {
        if (tid < o) red[tid] += red[tid + o];
        __syncthreads();
    }
    const float inv = rsqrtf(red[0] * (1.0f / HH) + 1e-5f);
#pragma unroll
    for (int i = 0; i < 4; i++) {
        int c = tid + i * 256;
        x[base + c] = (v[i] - mean) * inv * g[c] + b[c];
    }
}

__global__ void k_zero_counts()
{
    if (threadIdx.x < EE) g_counts[threadIdx.x] = 0;
}

__global__ void __launch_bounds__(256) k_gate(const float* __restrict__ x,
                                              const float* __restrict__ gw,
                                              const float* __restrict__ gb)
{
    const int t = blockIdx.x;
    const int tid = threadIdx.x;
    const int w = tid >> 5, lane = tid & 31;
    const float* xr = x + (long)t * HH;

    float s = 0.f;
    for (int j = lane; j < HH; j += 32) s += xr[j] * gw[(long)j * EE + w];
#pragma unroll
    for (int o = 16; o > 0; o >>= 1) s += __shfl_down_sync(0xFFFFFFFFu, s, o);

    __shared__ float lg[EE];
    if (lane == 0) lg[w] = s + gb[w];
    __syncthreads();

    if (tid == 0) {
        int i1 = 0;
        for (int e = 1; e < EE; e++) if (lg[e] > lg[i1]) i1 = e;
        int i2 = -1;
        for (int e = 0; e < EE; e++) {
            if (e == i1) continue;
            if (i2 < 0 || lg[e] > lg[i2]) i2 = e;
        }
        int p1 = atomicAdd(&g_counts[i1], 1);
        g_list[i1 * TT + p1] = t * 2 + 0;
        int p2 = atomicAdd(&g_counts[i2], 1);
        g_list[i2 * TT + p2] = t * 2 + 1;
    }
}

__global__ void __launch_bounds__(256) k_moe1(const float* __restrict__ x,
                                              const float* __restrict__ w1,
                                              const float* __restrict__ b1)
{
    const int e = blockIdx.z;
    const int cnt = g_counts[e];
    if ((int)blockIdx.y * BM >= cnt) return;
    gemm_tc_body<false, 3>(x, w1 + (long)e * HH * EH, b1 + (long)e * EH, g_h,
                           cnt, EH, HH, HH, EH, EH, 1.0f, 1,
                           g_list + e * TT, 1, g_list + e * TT);
}

__global__ void __launch_bounds__(256) k_moe2(const float* __restrict__ w2,
                                              const float* __restrict__ b2)
{
    const int e = blockIdx.z;
    const int cnt = g_counts[e];
    if ((int)blockIdx.y * BM >= cnt) return;
    gemm_tc_body<false, 3>(g_h, w2 + (long)e * EH * HH, b2 + (long)e * HH, g_y,
                           cnt, HH, EH, EH, HH, HH, 1.0f, 0,
                           g_list + e * TT, 2, g_list + e * TT);
}

__global__ void __launch_bounds__(256) k_combine(float* __restrict__ x)
{
    long i = (long)blockIdx.x * 256 + threadIdx.x;
    int t = (int)(i >> 10);
    int h = (int)(i & 1023);
    x[i] = g_y[((long)t * 2) * HH + h] + g_y[((long)t * 2 + 1) * HH + h];
}

// ---------------- host launcher ----------------
extern "C" void kernel_launch(void* const* d_in, const int* in_sizes, int n_in,
                              void* d_out, int out_size)
{
    (void)in_sizes; (void)n_in; (void)out_size;

    const int*   ids    = (const int*)d_in[0];
    const float* embed  = (const float*)d_in[1];
    const float* qkv_w  = (const float*)d_in[2];
    const float* qkv_b  = (const float*)d_in[3];
    const float* out_w  = (const float*)d_in[4];
    const float* out_b  = (const float*)d_in[5];
    const float* ln1g   = (const float*)d_in[6];
    const float* ln1b   = (const float*)d_in[7];
    const float* ffw1   = (const float*)d_in[8];
    const float* ffb1   = (const float*)d_in[9];
    const float* ffw2   = (const float*)d_in[10];
    const float* ffb2   = (const float*)d_in[11];
    const float* ln2g   = (const float*)d_in[12];
    const float* ln2b   = (const float*)d_in[13];
    const float* gw     = (const float*)d_in[14];
    const float* gb     = (const float*)d_in[15];
    const float* ew1    = (const float*)d_in[16];
    const float* eb1    = (const float*)d_in[17];
    const float* ew2    = (const float*)d_in[18];
    const float* eb2    = (const float*)d_in[19];
    const float* lmw    = (const float*)d_in[20];
    const float* lmb    = (const float*)d_in[21];
    float* out = (float*)d_out;

    float *p_x, *p_qkv, *p_ao, *p_buf, *p_ff, *p_scores;
    cudaGetSymbolAddress((void**)&p_x,      g_x);
    cudaGetSymbolAddress((void**)&p_qkv,    g_qkv);
    cudaGetSymbolAddress((void**)&p_ao,     g_ao);
    cudaGetSymbolAddress((void**)&p_buf,    g_buf);
    cudaGetSymbolAddress((void**)&p_ff,     g_ff);
    cudaGetSymbolAddress((void**)&p_scores, g_scores);

    k_embed<<<(TT * HH) / 256, 256>>>(ids, embed, p_x);

    for (int l = 0; l < LL; l++) {
        // QKV: x @ W^T + b
        k_gemm<true, 3><<<dim3(3 * HH / BN, TT / BM), 256>>>(
            p_x, qkv_w + (long)l * 3 * HH * HH, qkv_b + (long)l * 3 * HH, p_qkv,
            TT, 3 * HH, HH, HH, HH, 3 * HH, 1.0f, 0);

        // attention
        k_attn_scores<<<dim3(SS / BN, SS / BM, BB * NHD), 256>>>();
        k_softmax<<<BB * NHD * SS, 256>>>(p_scores, SS);
        k_attn_av<<<dim3(HD / BN, SS / BM, BB * NHD), 256>>>();

        // out proj
        k_gemm<true, 3><<<dim3(HH / BN, TT / BM), 256>>>(
            p_ao, out_w + (long)l * HH * HH, out_b + (long)l * HH, p_buf,
            TT, HH, HH, HH, HH, HH, 1.0f, 0);

        k_add_ln<<<TT, 256>>>(p_x, p_buf, ln1g + (long)l * HH, ln1b + (long)l * HH);

        // FFN
        k_gemm<false, 3><<<dim3(FF4 / BN, TT / BM), 256>>>(
            p_x, ffw1 + (long)l * HH * FF4, ffb1 + (long)l * FF4, p_ff,
            TT, FF4, HH, HH, FF4, FF4, 1.0f, 2);
        k_gemm<false, 3><<<dim3(HH / BN, TT / BM), 256>>>(
            p_ff, ffw2 + (long)l * FF4 * HH, ffb2 + (long)l * HH, p_buf,
            TT, HH, FF4, FF4, HH, HH, 1.0f, 0);

        k_add_ln<<<TT, 256>>>(p_x, p_buf, ln2g + (long)l * HH, ln2b + (long)l * HH);

        // MoE
        k_zero_counts<<<1, 32>>>();
        k_gate<<<TT, 256>>>(p_x, gw + (long)l * HH * EE, gb + (long)l * EE);
        k_moe1<<<dim3(EH / BN, TT / BM, EE), 256>>>(
            p_x, ew1 + (long)l * EE * HH * EH, eb1 + (long)l * EE * EH);
        k_moe2<<<dim3(HH / BN, TT / BM, EE), 256>>>(
            ew2 + (long)l * EE * EH * HH, eb2 + (long)l * EE * HH);
        k_combine<<<(TT * HH) / 256, 256>>>(p_x);
    }

    // lm head: post-routing, single-pass TF32 is accurate enough (~4e-4)
    k_gemm<false, 1><<<dim3(VV / BN, TT / BM), 256>>>(
        p_x, lmw, lmb, out, TT, VV, HH, HH, VV, VV, 1.0f, 0);
}

// round 14
// speedup vs baseline: 2.0416x; 1.6398x over previous
#include <cuda_runtime.h>
#include <cuda_bf16.h>
#include <math.h>
#include <stdint.h>

// ---------------- problem constants ----------------
#define BB   4
#define SS   1024
#define TT   4096        // B*S tokens
#define HH   1024
#define NHD  4           // heads
#define HD   256         // head dim
#define EE   8           // experts
#define KK   2           // top-k
#define VV   32000
#define LL   2
#define FF4  4096        // 4H
#define EH   2048        // 2H

// ---------------- device scratch (no allocations allowed) ----------------
__device__ float g_x[(size_t)TT * HH];
__device__ float g_qkv[(size_t)TT * 3 * HH];
__device__ float g_scores[(size_t)BB * NHD * SS * SS];
__device__ float g_ao[(size_t)TT * HH];
__device__ float g_buf[(size_t)TT * HH];
__device__ float g_ff[(size_t)TT * FF4];
__device__ float g_h[(size_t)TT * KK * EH];
__device__ float g_y[(size_t)TT * KK * HH];
__device__ int   g_list[EE * TT];
__device__ int   g_counts[EE];

// ---------------- helpers ----------------
__device__ __forceinline__ float gelu_exact(float v) {
    return 0.5f * v * (1.0f + erff(v * 0.70710678118654752440f));
}

__device__ __forceinline__ uint32_t f2tf(float f) {
    uint32_t u;
    asm("cvt.rna.tf32.f32 %0, %1;" : "=r"(u) : "f"(f));
    return u;
}

__device__ __forceinline__ void mma_tf32(float* d, const uint32_t* a, const uint32_t* b) {
    asm volatile(
        "mma.sync.aligned.m16n8k8.row.col.f32.tf32.tf32.f32 "
        "{%0,%1,%2,%3}, {%4,%5,%6,%7}, {%8,%9}, {%0,%1,%2,%3};"
        : "+f"(d[0]), "+f"(d[1]), "+f"(d[2]), "+f"(d[3])
        : "r"(a[0]), "r"(a[1]), "r"(a[2]), "r"(a[3]), "r"(b[0]), "r"(b[1]));
}

__device__ __forceinline__ void mma_bf16(float* d, const uint32_t* a, const uint32_t* b) {
    asm volatile(
        "mma.sync.aligned.m16n8k16.row.col.f32.bf16.bf16.f32 "
        "{%0,%1,%2,%3}, {%4,%5,%6,%7}, {%8,%9}, {%0,%1,%2,%3};"
        : "+f"(d[0]), "+f"(d[1]), "+f"(d[2]), "+f"(d[3])
        : "r"(a[0]), "r"(a[1]), "r"(a[2]), "r"(a[3]), "r"(b[0]), "r"(b[1]));
}

// split v into bf16 hi + bf16 lo (lo = bf16(v - hi)); pack two k-consecutive
// elements into one .b32 (low half = first element, matching mma fragment order)
__device__ __forceinline__ void split_pack(float v0, float v1, uint32_t& h, uint32_t& l) {
    __nv_bfloat16 h0 = __float2bfloat16_rn(v0);
    __nv_bfloat16 h1 = __float2bfloat16_rn(v1);
    __nv_bfloat16 l0 = __float2bfloat16_rn(v0 - __bfloat162float(h0));
    __nv_bfloat16 l1 = __float2bfloat16_rn(v1 - __bfloat162float(h1));
    h = (uint32_t)__bfloat16_as_ushort(h0) | ((uint32_t)__bfloat16_as_ushort(h1) << 16);
    l = (uint32_t)__bfloat16_as_ushort(l0) | ((uint32_t)__bfloat16_as_ushort(l1) << 16);
}

// XOR-swizzled smem index: row r (0..127), k-pair p (0..7). Conflict-free for
// mma fragment loads (banks (r&3)*8 + (p^(r&7)) distinct across a warp).
__device__ __forceinline__ int sx(int r, int p) { return r * 8 + (p ^ (r & 7)); }

#define BM 128
#define BN 128
#define BKT 16

// ================= bf16x3 split-precision 128x128x16 GEMM =================
// C[m,n] = act( alpha * sum_k A[m,k]*B(k,n) + bias[n] ),  ~2^-17 product error.
// TRANSB=false: B is KxN row-major.  TRANSB=true: B is NxK row-major (C=A*B^T).
// amap/amode: A-row gather (0 direct, 1 amap[r]>>1, 2 amap[r]). cmap: C scatter.
// Requirements: K%16==0, N%128==0, strides %4==0.
template<bool TRANSB>
__device__ __forceinline__ void gemm_bf3_body(
    const float* __restrict__ A, const float* __restrict__ B,
    const float* __restrict__ bias, float* __restrict__ C,
    int M, int N, int K, int lda, int ldb, int ldc,
    float alpha, int act,
    const int* __restrict__ amap, int amode, const int* __restrict__ cmap)
{
    __shared__ __align__(16) uint32_t Ah[2][BM * 8];
    __shared__ __align__(16) uint32_t Al[2][BM * 8];
    __shared__ __align__(16) uint32_t Bh[2][BN * 8];
    __shared__ __align__(16) uint32_t Bl[2][BN * 8];

    const int tid  = threadIdx.x;
    const int lane = tid & 31;
    const int warp = tid >> 5;
    const int wm   = warp >> 1;       // 0..3 (32 rows each)
    const int wn   = warp & 1;        // 0..1 (64 cols each)
    const int gid  = lane >> 2;       // 0..7
    const int ctg  = lane & 3;        // 0..3
    const int row0 = blockIdx.y * BM;
    const int col0 = blockIdx.x * BN;

    // ---- A global-load mapping: 2 x float4 per thread (k-consecutive) ----
    int  a_m[2], a_k[2];
    long a_base[2];
    bool a_ok[2];
#pragma unroll
    for (int i = 0; i < 2; i++) {
        int lin = tid + i * 256;
        a_m[i] = lin >> 2;                // 0..127
        a_k[i] = (lin & 3) * 4;           // 0,4,8,12
        int r = row0 + a_m[i];
        a_ok[i] = (r < M);
        long rr = r;
        if (a_ok[i]) {
            if (amode == 1)      rr = amap[r] >> 1;
            else if (amode == 2) rr = amap[r];
        }
        a_base[i] = rr * (long)lda + a_k[i];
    }

    // ---- B global-load mapping ----
    // TRANSB=true : float4 along k (rows = n), like A.
    // TRANSB=false: 4 strided scalar loads along k for one n (coalesced over n).
    int  b_n[2], b_k[2];
    long b_base[2];
#pragma unroll
    for (int i = 0; i < 2; i++) {
        int lin = tid + i * 256;          // 0..511
        if (TRANSB) {
            b_n[i] = lin >> 2;                         // n: 0..127
            b_k[i] = (lin & 3) * 4;                    // k: 0,4,8,12
            b_base[i] = (long)(col0 + b_n[i]) * ldb + b_k[i];
        } else {
            b_n[i] = lin & 127;                        // n: 0..127
            b_k[i] = (lin >> 7) * 4;                   // k: 0,4,8,12
            b_base[i] = (long)b_k[i] * ldb + col0 + b_n[i];
        }
    }

    float acc[2][8][4];
#pragma unroll
    for (int mt = 0; mt < 2; mt++)
#pragma unroll
        for (int nt = 0; nt < 8; nt++)
#pragma unroll
            for (int q = 0; q < 4; q++) acc[mt][nt][q] = 0.f;

    float4 ar[2];
    float  bq[2][4];

    auto ldg = [&](int k0) {
#pragma unroll
        for (int i = 0; i < 2; i++) {
            ar[i] = a_ok[i] ? *(const float4*)(A + a_base[i] + k0)
                            : make_float4(0.f, 0.f, 0.f, 0.f);
            if (TRANSB) {
                float4 bv = *(const float4*)(B + b_base[i] + k0);
                bq[i][0] = bv.x; bq[i][1] = bv.y; bq[i][2] = bv.z; bq[i][3] = bv.w;
            } else {
                const float* bp = B + b_base[i] + (long)k0 * ldb;
#pragma unroll
                for (int j = 0; j < 4; j++) bq[i][j] = bp[(long)j * ldb];
            }
        }
    };

    auto sts = [&](int buf) {
#pragma unroll
        for (int i = 0; i < 2; i++) {
            uint32_t h0, l0, h1, l1;
            split_pack(ar[i].x, ar[i].y, h0, l0);
            split_pack(ar[i].z, ar[i].w, h1, l1);
            int p = a_k[i] >> 1;
            Ah[buf][sx(a_m[i], p)]     = h0;
            Ah[buf][sx(a_m[i], p + 1)] = h1;
            Al[buf][sx(a_m[i], p)]     = l0;
            Al[buf][sx(a_m[i], p + 1)] = l1;

            split_pack(bq[i][0], bq[i][1], h0, l0);
            split_pack(bq[i][2], bq[i][3], h1, l1);
            int bp = b_k[i] >> 1;
            Bh[buf][sx(b_n[i], bp)]     = h0;
            Bh[buf][sx(b_n[i], bp + 1)] = h1;
            Bl[buf][sx(b_n[i], bp)]     = l0;
            Bl[buf][sx(b_n[i], bp + 1)] = l1;
        }
    };

    const int nk = K / BKT;
    ldg(0);
    sts(0);
    __syncthreads();

    int buf = 0;
    for (int kt = 0; kt < nk; kt++) {
        if (kt + 1 < nk) ldg((kt + 1) * BKT);

        // fragments (k16 covers the whole tile; no inner k loop)
        uint32_t ah[2][4], al[2][4];
#pragma unroll
        for (int mt = 0; mt < 2; mt++) {
            int r = wm * 32 + mt * 16 + gid;
            int i0 = sx(r, ctg), i1 = sx(r + 8, ctg);
            int i2 = sx(r, ctg + 4), i3 = sx(r + 8, ctg + 4);
            ah[mt][0] = Ah[buf][i0]; ah[mt][1] = Ah[buf][i1];
            ah[mt][2] = Ah[buf][i2]; ah[mt][3] = Ah[buf][i3];
            al[mt][0] = Al[buf][i0]; al[mt][1] = Al[buf][i1];
            al[mt][2] = Al[buf][i2]; al[mt][3] = Al[buf][i3];
        }
#pragma unroll
        for (int nt = 0; nt < 8; nt++) {
            int c = wn * 64 + nt * 8 + gid;
            int j0 = sx(c, ctg), j1 = sx(c, ctg + 4);
            uint32_t bh[2] = { Bh[buf][j0], Bh[buf][j1] };
            uint32_t bl[2] = { Bl[buf][j0], Bl[buf][j1] };
            mma_bf16(acc[0][nt], ah[0], bh);
            mma_bf16(acc[1][nt], ah[1], bh);
            mma_bf16(acc[0][nt], ah[0], bl);
            mma_bf16(acc[1][nt], ah[1], bl);
            mma_bf16(acc[0][nt], al[0], bh);
            mma_bf16(acc[1][nt], al[1], bh);
        }

        if (kt + 1 < nk) sts(buf ^ 1);
        __syncthreads();
        buf ^= 1;
    }

    // ---- epilogue ----
#pragma unroll
    for (int mt = 0; mt < 2; mt++) {
#pragma unroll
        for (int half = 0; half < 2; half++) {
            int r = row0 + wm * 32 + mt * 16 + gid + half * 8;
            if (r >= M) continue;
            long co = (long)(cmap ? cmap[r] : r) * (long)ldc;
#pragma unroll
            for (int nt = 0; nt < 8; nt++) {
                int c = col0 + wn * 64 + nt * 8 + ctg * 2;
                float v0 = acc[mt][nt][half * 2 + 0] * alpha;
                float v1 = acc[mt][nt][half * 2 + 1] * alpha;
                if (bias) { v0 += bias[c]; v1 += bias[c + 1]; }
                if (act == 1) {
                    v0 = fmaxf(v0, 0.f); v1 = fmaxf(v1, 0.f);
                } else if (act == 2) {
                    v0 = gelu_exact(v0); v1 = gelu_exact(v1);
                }
                *(float2*)(C + co + c) = make_float2(v0, v1);
            }
        }
    }
}

// ================= single-pass TF32 GEMM (lm_head only) =================
#define LDK 20
template<bool TRANSB>
__device__ __forceinline__ void gemm_tf1_body(
    const float* __restrict__ A, const float* __restrict__ B,
    const float* __restrict__ bias, float* __restrict__ C,
    int M, int N, int K, int lda, int ldb, int ldc,
    float alpha, int act)
{
    __shared__ __align__(16) float As[2][BM * LDK];
    __shared__ __align__(16) float Bs[2][BN * LDK];

    const int tid  = threadIdx.x;
    const int lane = tid & 31;
    const int warp = tid >> 5;
    const int wm   = warp >> 1;
    const int wn   = warp & 1;
    const int gid  = lane >> 2;
    const int ctg  = lane & 3;
    const int row0 = blockIdx.y * BM;
    const int col0 = blockIdx.x * BN;

    int  a_m[2], a_k[2];
    long a_base[2];
    bool a_ok[2];
#pragma unroll
    for (int i = 0; i < 2; i++) {
        int lin = tid + i * 256;
        a_m[i] = lin >> 2;
        a_k[i] = (lin & 3) * 4;
        int r = row0 + a_m[i];
        a_ok[i] = (r < M);
        a_base[i] = (long)r * lda + a_k[i];
    }

    int  b_i0[2], b_i1[2];
    long b_base[2];
#pragma unroll
    for (int i = 0; i < 2; i++) {
        int lin = tid + i * 256;
        if (TRANSB) {
            b_i0[i] = lin >> 2;
            b_i1[i] = (lin & 3) * 4;
            b_base[i] = (long)(col0 + b_i0[i]) * ldb + b_i1[i];
        } else {
            b_i0[i] = lin >> 5;
            b_i1[i] = (lin & 31) * 4;
            b_base[i] = (long)b_i0[i] * ldb + col0 + b_i1[i];
        }
    }

    float acc[2][8][4];
#pragma unroll
    for (int mt = 0; mt < 2; mt++)
#pragma unroll
        for (int nt = 0; nt < 8; nt++)
#pragma unroll
            for (int q = 0; q < 4; q++) acc[mt][nt][q] = 0.f;

    float4 ar[2], br[2];

    auto ldg = [&](int k0) {
#pragma unroll
        for (int i = 0; i < 2; i++) {
            ar[i] = a_ok[i] ? *(const float4*)(A + a_base[i] + k0)
                            : make_float4(0.f, 0.f, 0.f, 0.f);
            br[i] = *(const float4*)(B + b_base[i] + (TRANSB ? (long)k0 : (long)k0 * ldb));
        }
    };

    auto sts = [&](int buf) {
#pragma unroll
        for (int i = 0; i < 2; i++) {
            float* as = &As[buf][a_m[i] * LDK + a_k[i]];
            as[0] = ar[i].x; as[1] = ar[i].y; as[2] = ar[i].z; as[3] = ar[i].w;
            if (TRANSB) {
                float* bs = &Bs[buf][b_i0[i] * LDK + b_i1[i]];
                bs[0] = br[i].x; bs[1] = br[i].y; bs[2] = br[i].z; bs[3] = br[i].w;
            } else {
                int k = b_i0[i], n = b_i1[i];
                Bs[buf][(n + 0) * LDK + k] = br[i].x;
                Bs[buf][(n + 1) * LDK + k] = br[i].y;
                Bs[buf][(n + 2) * LDK + k] = br[i].z;
                Bs[buf][(n + 3) * LDK + k] = br[i].w;
            }
        }
    };

    const int nk = K / BKT;
    ldg(0);
    sts(0);
    __syncthreads();

    int buf = 0;
    for (int kt = 0; kt < nk; kt++) {
        if (kt + 1 < nk) ldg((kt + 1) * BKT);

#pragma unroll
        for (int kh = 0; kh < 2; kh++) {
            uint32_t afh[2][4];
#pragma unroll
            for (int mt = 0; mt < 2; mt++) {
                int r = wm * 32 + mt * 16 + gid;
                const float* a0 = &As[buf][r * LDK + kh * 8 + ctg];
                const float* a1 = &As[buf][(r + 8) * LDK + kh * 8 + ctg];
                afh[mt][0] = f2tf(a0[0]);
                afh[mt][1] = f2tf(a1[0]);
                afh[mt][2] = f2tf(a0[4]);
                afh[mt][3] = f2tf(a1[4]);
            }
#pragma unroll
            for (int nt = 0; nt < 8; nt++) {
                int c = wn * 64 + nt * 8 + gid;
                const float* bp = &Bs[buf][c * LDK + kh * 8 + ctg];
                uint32_t bfh[2] = { f2tf(bp[0]), f2tf(bp[4]) };
                mma_tf32(acc[0][nt], afh[0], bfh);
                mma_tf32(acc[1][nt], afh[1], bfh);
            }
        }

        if (kt + 1 < nk) sts(buf ^ 1);
        __syncthreads();
        buf ^= 1;
    }

#pragma unroll
    for (int mt = 0; mt < 2; mt++) {
#pragma unroll
        for (int half = 0; half < 2; half++) {
            int r = row0 + wm * 32 + mt * 16 + gid + half * 8;
            if (r >= M) continue;
            long co = (long)r * (long)ldc;
#pragma unroll
            for (int nt = 0; nt < 8; nt++) {
                int c = col0 + wn * 64 + nt * 8 + ctg * 2;
                float v0 = acc[mt][nt][half * 2 + 0] * alpha;
                float v1 = acc[mt][nt][half * 2 + 1] * alpha;
                if (bias) { v0 += bias[c]; v1 += bias[c + 1]; }
                *(float2*)(C + co + c) = make_float2(v0, v1);
            }
        }
    }
}

// ---------------- kernels ----------------
template<bool TRANSB>
__global__ void __launch_bounds__(256) k_gemm_bf3(
    const float* __restrict__ A, const float* __restrict__ B,
    const float* __restrict__ bias, float* __restrict__ C,
    int M, int N, int K, int lda, int ldb, int ldc, float alpha, int act)
{
    gemm_bf3_body<TRANSB>(A, B, bias, C, M, N, K, lda, ldb, ldc, alpha, act,
                          nullptr, 0, nullptr);
}

__global__ void __launch_bounds__(256) k_gemm_tf1(
    const float* __restrict__ A, const float* __restrict__ B,
    const float* __restrict__ bias, float* __restrict__ C,
    int M, int N, int K, int lda, int ldb, int ldc, float alpha, int act)
{
    gemm_tf1_body<false>(A, B, bias, C, M, N, K, lda, ldb, ldc, alpha, act);
}

__global__ void __launch_bounds__(256) k_embed(const int* __restrict__ ids,
                                               const float* __restrict__ emb,
                                               float* __restrict__ x)
{
    long i = (long)blockIdx.x * 256 + threadIdx.x;
    int t = (int)(i >> 10);
    int h = (int)(i & 1023);
    x[i] = emb[(long)ids[t] * HH + h];
}

__global__ void __launch_bounds__(256) k_attn_scores()
{
    const int z = blockIdx.z;
    const int b = z >> 2, h = z & 3;
    const float* A  = g_qkv + (long)b * SS * (3 * HH) + h * HD;  // Q
    const float* Bp = A + HH;                                    // K
    float* C = g_scores + (long)z * SS * SS;
    gemm_bf3_body<true>(A, Bp, nullptr, C, SS, SS, HD, 3 * HH, 3 * HH, SS,
                        0.0625f, 0, nullptr, 0, nullptr);
}

__global__ void __launch_bounds__(256) k_attn_av()
{
    const int z = blockIdx.z;
    const int b = z >> 2, h = z & 3;
    const float* A  = g_scores + (long)z * SS * SS;
    const float* Bp = g_qkv + (long)b * SS * (3 * HH) + 2 * HH + h * HD;
    float* C = g_ao + (long)b * SS * HH + h * HD;
    gemm_bf3_body<false>(A, Bp, nullptr, C, SS, HD, SS, SS, 3 * HH, HH,
                         1.0f, 0, nullptr, 0, nullptr);
}

__global__ void __launch_bounds__(256) k_softmax(float* __restrict__ data, int ncols)
{
    float* row = data + (long)blockIdx.x * ncols;
    const int tid = threadIdx.x;
    __shared__ float red[256];

    float m = -3.4e38f;
    for (int j = tid; j < ncols; j += 256) m = fmaxf(m, row[j]);
    red[tid] = m; __syncthreads();
    for (int o = 128; o > 0; o >>= 1) {
        if (tid < o) red[tid] = fmaxf(red[tid], red[tid + o]);
        __syncthreads();
    }
    m = red[0];
    __syncthreads();

    float s = 0.f;
    for (int j = tid; j < ncols; j += 256) {
        float e = expf(row[j] - m);
        row[j] = e;
        s += e;
    }
    red[tid] = s; __syncthreads();
    for (int o = 128; o > 0; o >>= 1) {
        if (tid < o) red[tid] += red[tid + o];
        __syncthreads();
    }
    const float inv = 1.f / red[0];
    for (int j = tid; j < ncols; j += 256) row[j] *= inv;
}

__global__ void __launch_bounds__(256) k_add_ln(float* __restrict__ x,
                                                const float* __restrict__ res,
                                                const float* __restrict__ g,
                                                const float* __restrict__ b)
{
    const int t = blockIdx.x;
    const int tid = threadIdx.x;
    const long base = (long)t * HH;
    __shared__ float red[256];

    float v[4];
    float s = 0.f;
#pragma unroll
    for (int i = 0; i < 4; i++) {
        v[i] = x[base + tid + i * 256] + res[base + tid + i * 256];
        s += v[i];
    }
    red[tid] = s; __syncthreads();
    for (int o = 128; o > 0; o >>= 1) {
        if (tid < o) red[tid] += red[tid + o];
        __syncthreads();
    }
    const float mean = red[0] * (1.0f / HH);
    __syncthreads();

    float s2 = 0.f;
#pragma unroll
    for (int i = 0; i < 4; i++) {
        float d = v[i] - mean;
        s2 += d * d;
    }
    red[tid] = s2; __syncthreads();
    for (int o = 128; o > 0; o >>= 1) {
        if (tid < o) red[tid] += red[tid + o];
        __syncthreads();
    }
    const float inv = rsqrtf(red[0] * (1.0f / HH) + 1e-5f);
#pragma unroll
    for (int i = 0; i < 4; i++) {
        int c = tid + i * 256;
        x[base + c] = (v[i] - mean) * inv * g[c] + b[c];
    }
}

__global__ void k_zero_counts()
{
    if (threadIdx.x < EE) g_counts[threadIdx.x] = 0;
}

__global__ void __launch_bounds__(256) k_gate(const float* __restrict__ x,
                                              const float* __restrict__ gw,
                                              const float* __restrict__ gb)
{
    const int t = blockIdx.x;
    const int tid = threadIdx.x;
    const int w = tid >> 5, lane = tid & 31;
    const float* xr = x + (long)t * HH;

    float s = 0.f;
    for (int j = lane; j < HH; j += 32) s += xr[j] * gw[(long)j * EE + w];
#pragma unroll
    for (int o = 16; o > 0; o >>= 1) s += __shfl_down_sync(0xFFFFFFFFu, s, o);

    __shared__ float lg[EE];
    if (lane == 0) lg[w] = s + gb[w];
    __syncthreads();

    if (tid == 0) {
        int i1 = 0;
        for (int e = 1; e < EE; e++) if (lg[e] > lg[i1]) i1 = e;
        int i2 = -1;
        for (int e = 0; e < EE; e++) {
            if (e == i1) continue;
            if (i2 < 0 || lg[e] > lg[i2]) i2 = e;
        }
        int p1 = atomicAdd(&g_counts[i1], 1);
        g_list[i1 * TT + p1] = t * 2 + 0;
        int p2 = atomicAdd(&g_counts[i2], 1);
        g_list[i2 * TT + p2] = t * 2 + 1;
    }
}

__global__ void __launch_bounds__(256) k_moe1(const float* __restrict__ x,
                                              const float* __restrict__ w1,
                                              const float* __restrict__ b1)
{
    const int e = blockIdx.z;
    const int cnt = g_counts[e];
    if ((int)blockIdx.y * BM >= cnt) return;
    gemm_bf3_body<false>(x, w1 + (long)e * HH * EH, b1 + (long)e * EH, g_h,
                         cnt, EH, HH, HH, EH, EH, 1.0f, 1,
                         g_list + e * TT, 1, g_list + e * TT);
}

__global__ void __launch_bounds__(256) k_moe2(const float* __restrict__ w2,
                                              const float* __restrict__ b2)
{
    const int e = blockIdx.z;
    const int cnt = g_counts[e];
    if ((int)blockIdx.y * BM >= cnt) return;
    gemm_bf3_body<false>(g_h, w2 + (long)e * EH * HH, b2 + (long)e * HH, g_y,
                         cnt, HH, EH, EH, HH, HH, 1.0f, 0,
                         g_list + e * TT, 2, g_list + e * TT);
}

__global__ void __launch_bounds__(256) k_combine(float* __restrict__ x)
{
    long i = (long)blockIdx.x * 256 + threadIdx.x;
    int t = (int)(i >> 10);
    int h = (int)(i & 1023);
    x[i] = g_y[((long)t * 2) * HH + h] + g_y[((long)t * 2 + 1) * HH + h];
}

// ---------------- host launcher ----------------
extern "C" void kernel_launch(void* const* d_in, const int* in_sizes, int n_in,
                              void* d_out, int out_size)
{
    (void)in_sizes; (void)n_in; (void)out_size;

    const int*   ids    = (const int*)d_in[0];
    const float* embed  = (const float*)d_in[1];
    const float* qkv_w  = (const float*)d_in[2];
    const float* qkv_b  = (const float*)d_in[3];
    const float* out_w  = (const float*)d_in[4];
    const float* out_b  = (const float*)d_in[5];
    const float* ln1g   = (const float*)d_in[6];
    const float* ln1b   = (const float*)d_in[7];
    const float* ffw1   = (const float*)d_in[8];
    const float* ffb1   = (const float*)d_in[9];
    const float* ffw2   = (const float*)d_in[10];
    const float* ffb2   = (const float*)d_in[11];
    const float* ln2g   = (const float*)d_in[12];
    const float* ln2b   = (const float*)d_in[13];
    const float* gw     = (const float*)d_in[14];
    const float* gb     = (const float*)d_in[15];
    const float* ew1    = (const float*)d_in[16];
    const float* eb1    = (const float*)d_in[17];
    const float* ew2    = (const float*)d_in[18];
    const float* eb2    = (const float*)d_in[19];
    const float* lmw    = (const float*)d_in[20];
    const float* lmb    = (const float*)d_in[21];
    float* out = (float*)d_out;

    float *p_x, *p_qkv, *p_ao, *p_buf, *p_ff, *p_scores;
    cudaGetSymbolAddress((void**)&p_x,      g_x);
    cudaGetSymbolAddress((void**)&p_qkv,    g_qkv);
    cudaGetSymbolAddress((void**)&p_ao,     g_ao);
    cudaGetSymbolAddress((void**)&p_buf,    g_buf);
    cudaGetSymbolAddress((void**)&p_ff,     g_ff);
    cudaGetSymbolAddress((void**)&p_scores, g_scores);

    k_embed<<<(TT * HH) / 256, 256>>>(ids, embed, p_x);

    for (int l = 0; l < LL; l++) {
        // QKV: x @ W^T + b
        k_gemm_bf3<true><<<dim3(3 * HH / BN, TT / BM), 256>>>(
            p_x, qkv_w + (long)l * 3 * HH * HH, qkv_b + (long)l * 3 * HH, p_qkv,
            TT, 3 * HH, HH, HH, HH, 3 * HH, 1.0f, 0);

        // attention
        k_attn_scores<<<dim3(SS / BN, SS / BM, BB * NHD), 256>>>();
        k_softmax<<<BB * NHD * SS, 256>>>(p_scores, SS);
        k_attn_av<<<dim3(HD / BN, SS / BM, BB * NHD), 256>>>();

        // out proj
        k_gemm_bf3<true><<<dim3(HH / BN, TT / BM), 256>>>(
            p_ao, out_w + (long)l * HH * HH, out_b + (long)l * HH, p_buf,
            TT, HH, HH, HH, HH, HH, 1.0f, 0);

        k_add_ln<<<TT, 256>>>(p_x, p_buf, ln1g + (long)l * HH, ln1b + (long)l * HH);

        // FFN
        k_gemm_bf3<false><<<dim3(FF4 / BN, TT / BM), 256>>>(
            p_x, ffw1 + (long)l * HH * FF4, ffb1 + (long)l * FF4, p_ff,
            TT, FF4, HH, HH, FF4, FF4, 1.0f, 2);
        k_gemm_bf3<false><<<dim3(HH / BN, TT / BM), 256>>>(
            p_ff, ffw2 + (long)l * FF4 * HH, ffb2 + (long)l * HH, p_buf,
            TT, HH, FF4, FF4, HH, HH, 1.0f, 0);

        k_add_ln<<<TT, 256>>>(p_x, p_buf, ln2g + (long)l * HH, ln2b + (long)l * HH);

        // MoE
        k_zero_counts<<<1, 32>>>();
        k_gate<<<TT, 256>>>(p_x, gw + (long)l * HH * EE, gb + (long)l * EE);
        k_moe1<<<dim3(EH / BN, TT / BM, EE), 256>>>(
            p_x, ew1 + (long)l * EE * HH * EH, eb1 + (long)l * EE * EH);
        k_moe2<<<dim3(HH / BN, TT / BM, EE), 256>>>(
            ew2 + (long)l * EE * EH * HH, eb2 + (long)l * EE * HH);
        k_combine<<<(TT * HH) / 256, 256>>>(p_x);
    }

    // lm head: post-routing, single-pass TF32 (~3e-4, under threshold)
    k_gemm_tf1<<<dim3(VV / BN, TT / BM), 256>>>(
        p_x, lmw, lmb, out, TT, VV, HH, HH, VV, VV, 1.0f, 0);
}

// round 16
// speedup vs baseline: 2.7225x; 1.3335x over previous
#include <cuda_runtime.h>
#include <cuda_bf16.h>
#include <math.h>
#include <stdint.h>

// ---------------- problem constants ----------------
#define BB   4
#define SS   1024
#define TT   4096        // B*S tokens
#define HH   1024
#define NHD  4           // heads
#define HD   256         // head dim
#define EE   8           // experts
#define KK   2           // top-k
#define VV   32000
#define LL   2
#define FF4  4096        // 4H
#define EH   2048        // 2H

// ---------------- device scratch (no allocations allowed) ----------------
// fp32
__device__ float g_x[(size_t)TT * HH];
__device__ float g_scores[(size_t)BB * NHD * SS * SS];
__device__ float g_buf[(size_t)TT * HH];
__device__ float g_y[(size_t)TT * KK * HH];
__device__ int   g_list[EE * TT];
__device__ int   g_counts[EE];
// bf16 hi/lo planes
__device__ __nv_bfloat16 g_xh[(size_t)TT * HH],        g_xl[(size_t)TT * HH];
__device__ __nv_bfloat16 g_qkvh[(size_t)TT * 3 * HH],  g_qkvl[(size_t)TT * 3 * HH];
__device__ __nv_bfloat16 g_sph[(size_t)BB * NHD * SS * SS], g_spl[(size_t)BB * NHD * SS * SS];
__device__ __nv_bfloat16 g_vth[(size_t)BB * NHD * HD * SS], g_vtl[(size_t)BB * NHD * HD * SS];
__device__ __nv_bfloat16 g_aoh[(size_t)TT * HH],       g_aol[(size_t)TT * HH];
__device__ __nv_bfloat16 g_ffh[(size_t)TT * FF4],      g_ffl[(size_t)TT * FF4];
__device__ __nv_bfloat16 g_hh[(size_t)TT * KK * EH],   g_hl[(size_t)TT * KK * EH];
__device__ __nv_bfloat16 g_wbh[(size_t)VV * HH + 1024], g_wbl[(size_t)VV * HH + 1024];

// ---------------- helpers ----------------
__device__ __forceinline__ float gelu_exact(float v) {
    return 0.5f * v * (1.0f + erff(v * 0.70710678118654752440f));
}

__device__ __forceinline__ void split1(float v, __nv_bfloat16& h, __nv_bfloat16& l) {
    h = __float2bfloat16_rn(v);
    l = __float2bfloat16_rn(v - __bfloat162float(h));
}

__device__ __forceinline__ void split_pack(float v0, float v1, uint32_t& h, uint32_t& l) {
    __nv_bfloat16 h0, l0, h1, l1;
    split1(v0, h0, l0);
    split1(v1, h1, l1);
    h = (uint32_t)__bfloat16_as_ushort(h0) | ((uint32_t)__bfloat16_as_ushort(h1) << 16);
    l = (uint32_t)__bfloat16_as_ushort(l0) | ((uint32_t)__bfloat16_as_ushort(l1) << 16);
}

__device__ __forceinline__ void mma_bf16(float* d, const uint32_t* a, const uint32_t* b) {
    asm volatile(
        "mma.sync.aligned.m16n8k16.row.col.f32.bf16.bf16.f32 "
        "{%0,%1,%2,%3}, {%4,%5,%6,%7}, {%8,%9}, {%0,%1,%2,%3};"
        : "+f"(d[0]), "+f"(d[1]), "+f"(d[2]), "+f"(d[3])
        : "r"(a[0]), "r"(a[1]), "r"(a[2]), "r"(a[3]), "r"(b[0]), "r"(b[1]));
}

__device__ __forceinline__ uint32_t s2u(const void* p) {
    uint32_t a;
    asm("{ .reg .u64 t; cvta.to.shared.u64 t, %1; cvt.u32.u64 %0, t; }"
        : "=r"(a) : "l"(p));
    return a;
}

__device__ __forceinline__ void cpa16(uint32_t dst, const void* src) {
    asm volatile("cp.async.cg.shared.global [%0], [%1], 16;" :: "r"(dst), "l"(src));
}
#define CP_COMMIT() asm volatile("cp.async.commit_group;" ::: "memory")
#define CP_WAIT(n)  asm volatile("cp.async.wait_group %0;" :: "n"(n) : "memory")

__device__ __forceinline__ void ldsm4(uint32_t* r, uint32_t a) {
    asm volatile("ldmatrix.sync.aligned.m8n8.x4.shared.b16 {%0,%1,%2,%3}, [%4];"
        : "=r"(r[0]), "=r"(r[1]), "=r"(r[2]), "=r"(r[3]) : "r"(a));
}

// ================= bf16x3 GEMM engine: 128x128 tile, k64 stages =================
// C[m,n] = act( alpha * sum_k A[m,k]*B[n,k] + bias[n] )
// A: hi/lo bf16 planes, row stride lda (elements). B: hi/lo planes [N][K], stride ldb.
// Outputs: Cf (fp32) and/or Ch/Cl (bf16 planes), row stride ldc.
// amap/amode row gather (0 direct, 1 amap[r]>>1, 2 amap[r]); cmap row scatter.
// Requirements: K%64==0, N%128==0, all strides even.
#define TM 128
#define TN 128
#define TK 64
#define SA_H 0
#define SA_L 16384
#define SB_H 32768
#define SB_L 49152
#define STAGE_BYTES 65536
#define SMEM_BYTES  131072

__device__ void gemm5(
    const __nv_bfloat16* __restrict__ Ah, const __nv_bfloat16* __restrict__ Al, int lda,
    const __nv_bfloat16* __restrict__ Bh, const __nv_bfloat16* __restrict__ Bl, int ldb,
    const float* __restrict__ bias,
    float* __restrict__ Cf, __nv_bfloat16* __restrict__ Ch, __nv_bfloat16* __restrict__ Cl,
    int ldc, int M, int N, int K, float alpha, int act,
    const int* __restrict__ amap, int amode, const int* __restrict__ cmap)
{
    extern __shared__ char smem[];
    const uint32_t sb = s2u(smem);
    const int tid  = threadIdx.x;
    const int lane = tid & 31, warp = tid >> 5;
    const int wm = warp >> 1, wn = warp & 1;      // warp tile: m32 x n64
    const int row0 = blockIdx.y * TM, col0 = blockIdx.x * TN;

    // per-thread cp.async descriptors: 4 (row, chunk) pairs covering 128x8 chunks
    long a_src[4], b_src[4];
    uint32_t sdst[4];
#pragma unroll
    for (int i = 0; i < 4; i++) {
        int lin = tid + i * 256;          // 0..1023
        int r = lin >> 3, c = lin & 7;
        int rg = row0 + r; if (rg > M - 1) rg = M - 1;
        long rr = rg;
        if (amode == 1)      rr = amap[rg] >> 1;
        else if (amode == 2) rr = amap[rg];
        a_src[i] = rr * (long)lda + c * 8;
        b_src[i] = (long)(col0 + r) * ldb + c * 8;
        sdst[i]  = (uint32_t)(r * 128 + ((c ^ (r & 7)) * 16));
    }

    float acc[2][8][4];
#pragma unroll
    for (int mt = 0; mt < 2; mt++)
#pragma unroll
        for (int nt = 0; nt < 8; nt++)
#pragma unroll
            for (int q = 0; q < 4; q++) acc[mt][nt][q] = 0.f;

    const int nst = K / TK;   // >= 4 for all call sites

    // issue stage s into buffer (s&1) at k offset k0
#define ISSUE(bufbit, k0) do { \
        uint32_t _b = sb + (bufbit) * STAGE_BYTES; \
        _Pragma("unroll") \
        for (int i = 0; i < 4; i++) { \
            cpa16(_b + SA_H + sdst[i], Ah + a_src[i] + (k0)); \
            cpa16(_b + SA_L + sdst[i], Al + a_src[i] + (k0)); \
            cpa16(_b + SB_H + sdst[i], Bh + b_src[i] + (k0)); \
            cpa16(_b + SB_L + sdst[i], Bl + b_src[i] + (k0)); \
        } \
        CP_COMMIT(); \
    } while (0)

    ISSUE(0, 0);
    ISSUE(1, TK);
    CP_WAIT(1);
    __syncthreads();

    const int arow = wm * 32 + (lane & 15);
    const int brow = wn * 64 + (lane & 15);
    const int ksel = lane >> 4;             // 0/1: k8 half selector

    for (int s = 0; s < nst; s++) {
        const uint32_t base = sb + (s & 1) * STAGE_BYTES;
#pragma unroll
        for (int ks = 0; ks < 4; ks++) {
            uint32_t ah[2][4], alr[2][4];
#pragma unroll
            for (int mt = 0; mt < 2; mt++) {
                int r = arow + mt * 16;
                uint32_t ad = base + SA_H + r * 128 + (((ks * 2 + ksel) ^ (r & 7)) * 16);
                ldsm4(ah[mt], ad);
                ldsm4(alr[mt], ad + (SA_L - SA_H));
            }
#pragma unroll
            for (int j = 0; j < 4; j++) {
                uint32_t bh4[4], bl4[4];
                int r = brow + j * 16;
                uint32_t bd = base + SB_H + r * 128 + (((ks * 2 + ksel) ^ (r & 7)) * 16);
                ldsm4(bh4, bd);
                ldsm4(bl4, bd + (SB_L - SB_H));
                // tile t (n8): b-pair = {reg[t], reg[t+2]}
#pragma unroll
                for (int t = 0; t < 2; t++) {
                    int nt = j * 2 + t;
                    uint32_t bh2[2] = { bh4[t], bh4[t + 2] };
                    uint32_t bl2[2] = { bl4[t], bl4[t + 2] };
                    mma_bf16(acc[0][nt], ah[0], bh2);
                    mma_bf16(acc[1][nt], ah[1], bh2);
                    mma_bf16(acc[0][nt], ah[0], bl2);
                    mma_bf16(acc[1][nt], ah[1], bl2);
                    mma_bf16(acc[0][nt], alr[0], bh2);
                    mma_bf16(acc[1][nt], alr[1], bh2);
                }
            }
        }
        __syncthreads();           // all warps done with this buffer
        if (s + 2 < nst) {
            ISSUE(s & 1, (s + 2) * TK);
            CP_WAIT(1);            // next buffer's data complete
            __syncthreads();
        } else if (s + 1 < nst) {
            CP_WAIT(0);
            __syncthreads();
        }
    }

    // ---- epilogue: fragment registers -> C ----
    const int gid = lane >> 2, ctg = lane & 3;
#pragma unroll
    for (int mt = 0; mt < 2; mt++) {
#pragma unroll
        for (int half = 0; half < 2; half++) {
            int rg = row0 + wm * 32 + mt * 16 + gid + half * 8;
            if (rg >= M) continue;
            long co = (long)(cmap ? cmap[rg] : rg) * (long)ldc;
#pragma unroll
            for (int nt = 0; nt < 8; nt++) {
                int c = col0 + wn * 64 + nt * 8 + ctg * 2;
                float v0 = acc[mt][nt][half * 2 + 0] * alpha;
                float v1 = acc[mt][nt][half * 2 + 1] * alpha;
                if (bias) { v0 += bias[c]; v1 += bias[c + 1]; }
                if (act == 1) {
                    v0 = fmaxf(v0, 0.f); v1 = fmaxf(v1, 0.f);
                } else if (act == 2) {
                    v0 = gelu_exact(v0); v1 = gelu_exact(v1);
                }
                if (Cf) *(float2*)(Cf + co + c) = make_float2(v0, v1);
                if (Ch) {
                    uint32_t hw, lw;
                    split_pack(v0, v1, hw, lw);
                    *(uint32_t*)(Ch + co + c) = hw;
                    *(uint32_t*)(Cl + co + c) = lw;
                }
            }
        }
    }
#undef ISSUE
}

// ---------------- GEMM wrappers ----------------
__global__ void __launch_bounds__(256) k_gemm(
    const __nv_bfloat16* Ah, const __nv_bfloat16* Al, int lda,
    const __nv_bfloat16* Bh, const __nv_bfloat16* Bl, int ldb,
    const float* bias, float* Cf, __nv_bfloat16* Ch, __nv_bfloat16* Cl, int ldc,
    int M, int N, int K, float alpha, int act)
{
    gemm5(Ah, Al, lda, Bh, Bl, ldb, bias, Cf, Ch, Cl, ldc,
          M, N, K, alpha, act, nullptr, 0, nullptr);
}

__global__ void __launch_bounds__(256) k_scores()
{
    int z = blockIdx.z, b = z >> 2, h = z & 3;
    long qo = (long)b * SS * 3 * HH + (long)h * HD;
    gemm5(g_qkvh + qo, g_qkvl + qo, 3 * HH,
          g_qkvh + qo + HH, g_qkvl + qo + HH, 3 * HH,
          nullptr, g_scores + (long)z * SS * SS, nullptr, nullptr, SS,
          SS, SS, HD, 0.0625f, 0, nullptr, 0, nullptr);
}

__global__ void __launch_bounds__(256) k_av()
{
    int z = blockIdx.z, b = z >> 2, h = z & 3;
    long po = (long)z * SS * SS;
    long vo = (long)z * HD * SS;
    long ao = (long)b * SS * HH + (long)h * HD;
    gemm5(g_sph + po, g_spl + po, SS, g_vth + vo, g_vtl + vo, SS,
          nullptr, nullptr, g_aoh + ao, g_aol + ao, HH,
          SS, HD, SS, 1.0f, 0, nullptr, 0, nullptr);
}

__global__ void __launch_bounds__(256) k_moe1(const float* __restrict__ eb1)
{
    int e = blockIdx.z;
    int cnt = g_counts[e];
    if ((int)blockIdx.y * TM >= cnt) return;
    gemm5(g_xh, g_xl, HH,
          g_wbh + (long)e * EH * HH, g_wbl + (long)e * EH * HH, HH,
          eb1 + e * EH, nullptr, g_hh, g_hl, EH,
          cnt, EH, HH, 1.0f, 1, g_list + e * TT, 1, g_list + e * TT);
}

__global__ void __launch_bounds__(256) k_moe2(const float* __restrict__ eb2)
{
    int e = blockIdx.z;
    int cnt = g_counts[e];
    if ((int)blockIdx.y * TM >= cnt) return;
    gemm5(g_hh, g_hl, EH,
          g_wbh + (long)e * HH * EH, g_wbl + (long)e * HH * EH, EH,
          eb2 + e * HH, g_y, nullptr, nullptr, HH,
          cnt, HH, EH, 1.0f, 0, g_list + e * TT, 2, g_list + e * TT);
}

// ---------------- conversion kernels ----------------
// fp32 -> bf16 hi/lo planes (same layout)
__global__ void __launch_bounds__(256) k_conv_rm(const float* __restrict__ src,
                                                 __nv_bfloat16* __restrict__ dh,
                                                 __nv_bfloat16* __restrict__ dl)
{
    long i4 = ((long)blockIdx.x * 256 + threadIdx.x) * 4;
    float4 v = *(const float4*)(src + i4);
    uint32_t h0, l0, h1, l1;
    split_pack(v.x, v.y, h0, l0);
    split_pack(v.z, v.w, h1, l1);
    *(uint2*)(dh + i4) = make_uint2(h0, h1);
    *(uint2*)(dl + i4) = make_uint2(l0, l1);
}

// fp32 [R][C] -> bf16 hi/lo planes [C][R] (transpose); blockIdx.z offsets by z*R*C
__global__ void __launch_bounds__(256) k_conv_tr(const float* __restrict__ src, int R, int C,
                                                 __nv_bfloat16* __restrict__ dh,
                                                 __nv_bfloat16* __restrict__ dl)
{
    __shared__ float t[32][33];
    long zo = (long)blockIdx.z * R * C;
    int c0 = blockIdx.x * 32, r0 = blockIdx.y * 32;
    int tx = threadIdx.x & 31, ty = threadIdx.x >> 5;
#pragma unroll
    for (int j = 0; j < 4; j++)
        t[ty + j * 8][tx] = src[zo + (long)(r0 + ty + j * 8) * C + c0 + tx];
    __syncthreads();
#pragma unroll
    for (int j = 0; j < 4; j++) {
        float v = t[tx][ty + j * 8];
        __nv_bfloat16 h, l;
        split1(v, h, l);
        long o = zo + (long)(c0 + ty + j * 8) * R + r0 + tx;
        dh[o] = h; dl[o] = l;
    }
}

// transpose the V region of qkv planes: per z=(b,h): [S][HD] (stride 3H) -> [HD][S]
__global__ void __launch_bounds__(256) k_conv_vt()
{
    __shared__ __nv_bfloat16 th[32][34], tl[32][34];
    int z = blockIdx.z, b = z >> 2, h = z & 3;
    long sbase = (long)b * SS * 3 * HH + 2 * HH + (long)h * HD;
    long dbase = (long)z * HD * SS;
    int d0 = blockIdx.x * 32, s0 = blockIdx.y * 32;
    int tx = threadIdx.x & 31, ty = threadIdx.x >> 5;
#pragma unroll
    for (int j = 0; j < 4; j++) {
        long so = sbase + (long)(s0 + ty + j * 8) * (3 * HH) + d0 + tx;
        th[ty + j * 8][tx] = g_qkvh[so];
        tl[ty + j * 8][tx] = g_qkvl[so];
    }
    __syncthreads();
#pragma unroll
    for (int j = 0; j < 4; j++) {
        long o = dbase + (long)(d0 + ty + j * 8) * SS + s0 + tx;
        g_vth[o] = th[tx][ty + j * 8];
        g_vtl[o] = tl[tx][ty + j * 8];
    }
}

// ---------------- elementwise / reduction kernels ----------------
__global__ void __launch_bounds__(256) k_embed(const int* __restrict__ ids,
                                               const float* __restrict__ emb)
{
    long i = (long)blockIdx.x * 256 + threadIdx.x;
    int t = (int)(i >> 10);
    int h = (int)(i & 1023);
    float v = emb[(long)ids[t] * HH + h];
    g_x[i] = v;
    __nv_bfloat16 hb, lb;
    split1(v, hb, lb);
    g_xh[i] = hb; g_xl[i] = lb;
}

// softmax over scores rows (1024 cols); writes P planes
__global__ void __launch_bounds__(256) k_softmax()
{
    const long base = (long)blockIdx.x * SS;
    const float* row = g_scores + base;
    const int tid = threadIdx.x;
    __shared__ float red[256];

    float v[4];
#pragma unroll
    for (int i = 0; i < 4; i++) v[i] = row[tid + i * 256];

    float m = fmaxf(fmaxf(v[0], v[1]), fmaxf(v[2], v[3]));
    red[tid] = m; __syncthreads();
    for (int o = 128; o > 0; o >>= 1) {
        if (tid < o) red[tid] = fmaxf(red[tid], red[tid + o]);
        __syncthreads();
    }
    m = red[0];
    __syncthreads();

    float s = 0.f;
#pragma unroll
    for (int i = 0; i < 4; i++) { v[i] = expf(v[i] - m); s += v[i]; }
    red[tid] = s; __syncthreads();
    for (int o = 128; o > 0; o >>= 1) {
        if (tid < o) red[tid] += red[tid + o];
        __syncthreads();
    }
    const float inv = 1.f / red[0];
#pragma unroll
    for (int i = 0; i < 4; i++) {
        __nv_bfloat16 hb, lb;
        split1(v[i] * inv, hb, lb);
        g_sph[base + tid + i * 256] = hb;
        g_spl[base + tid + i * 256] = lb;
    }
}

// x = LN(x + res); writes fp32 x and planes
__global__ void __launch_bounds__(256) k_add_ln(const float* __restrict__ res,
                                                const float* __restrict__ g,
                                                const float* __restrict__ b)
{
    const int t = blockIdx.x;
    const int tid = threadIdx.x;
    const long base = (long)t * HH;
    __shared__ float red[256];

    float v[4];
    float s = 0.f;
#pragma unroll
    for (int i = 0; i < 4; i++) {
        v[i] = g_x[base + tid + i * 256] + res[base + tid + i * 256];
        s += v[i];
    }
    red[tid] = s; __syncthreads();
    for (int o = 128; o > 0; o >>= 1) {
        if (tid < o) red[tid] += red[tid + o];
        __syncthreads();
    }
    const float mean = red[0] * (1.0f / HH);
    __syncthreads();

    float s2 = 0.f;
#pragma unroll
    for (int i = 0; i < 4; i++) {
        float d = v[i] - mean;
        s2 += d * d;
    }
    red[tid] = s2; __syncthreads();
    for (int o = 128; o > 0; o >>= 1) {
        if (tid < o) red[tid] += red[tid + o];
        __syncthreads();
    }
    const float inv = rsqrtf(red[0] * (1.0f / HH) + 1e-5f);
#pragma unroll
    for (int i = 0; i < 4; i++) {
        int c = tid + i * 256;
        float o = (v[i] - mean) * inv * g[c] + b[c];
        g_x[base + c] = o;
        __nv_bfloat16 hb, lb;
        split1(o, hb, lb);
        g_xh[base + c] = hb; g_xl[base + c] = lb;
    }
}

__global__ void k_zero_counts()
{
    if (threadIdx.x < EE) g_counts[threadIdx.x] = 0;
}

__global__ void __launch_bounds__(256) k_gate(const float* __restrict__ gw,
                                              const float* __restrict__ gb)
{
    const int t = blockIdx.x;
    const int tid = threadIdx.x;
    const int w = tid >> 5, lane = tid & 31;
    const float* xr = g_x + (long)t * HH;

    float s = 0.f;
    for (int j = lane; j < HH; j += 32) s += xr[j] * gw[(long)j * EE + w];
#pragma unroll
    for (int o = 16; o > 0; o >>= 1) s += __shfl_down_sync(0xFFFFFFFFu, s, o);

    __shared__ float lg[EE];
    if (lane == 0) lg[w] = s + gb[w];
    __syncthreads();

    if (tid == 0) {
        int i1 = 0;
        for (int e = 1; e < EE; e++) if (lg[e] > lg[i1]) i1 = e;
        int i2 = -1;
        for (int e = 0; e < EE; e++) {
            if (e == i1) continue;
            if (i2 < 0 || lg[e] > lg[i2]) i2 = e;
        }
        int p1 = atomicAdd(&g_counts[i1], 1);
        g_list[i1 * TT + p1] = t * 2 + 0;
        int p2 = atomicAdd(&g_counts[i2], 1);
        g_list[i2 * TT + p2] = t * 2 + 1;
    }
}

// x = y[slot 2t] + y[slot 2t+1]; writes fp32 x and planes
__global__ void __launch_bounds__(256) k_combine()
{
    long i = (long)blockIdx.x * 256 + threadIdx.x;
    int t = (int)(i >> 10);
    int h = (int)(i & 1023);
    float v = g_y[((long)t * 2) * HH + h] + g_y[((long)t * 2 + 1) * HH + h];
    g_x[i] = v;
    __nv_bfloat16 hb, lb;
    split1(v, hb, lb);
    g_xh[i] = hb; g_xl[i] = lb;
}

// ---------------- host launcher ----------------
extern "C" void kernel_launch(void* const* d_in, const int* in_sizes, int n_in,
                              void* d_out, int out_size)
{
    (void)in_sizes; (void)n_in; (void)out_size;

    const int*   ids    = (const int*)d_in[0];
    const float* embed  = (const float*)d_in[1];
    const float* qkv_w  = (const float*)d_in[2];
    const float* qkv_b  = (const float*)d_in[3];
    const float* out_w  = (const float*)d_in[4];
    const float* out_b  = (const float*)d_in[5];
    const float* ln1g   = (const float*)d_in[6];
    const float* ln1b   = (const float*)d_in[7];
    const float* ffw1   = (const float*)d_in[8];
    const float* ffb1   = (const float*)d_in[9];
    const float* ffw2   = (const float*)d_in[10];
    const float* ffb2   = (const float*)d_in[11];
    const float* ln2g   = (const float*)d_in[12];
    const float* ln2b   = (const float*)d_in[13];
    const float* gw     = (const float*)d_in[14];
    const float* gb     = (const float*)d_in[15];
    const float* ew1    = (const float*)d_in[16];
    const float* eb1    = (const float*)d_in[17];
    const float* ew2    = (const float*)d_in[18];
    const float* eb2    = (const float*)d_in[19];
    const float* lmw    = (const float*)d_in[20];
    const float* lmb    = (const float*)d_in[21];
    float* out = (float*)d_out;

    float *p_buf;
    __nv_bfloat16 *p_xh, *p_xl, *p_qkvh, *p_qkvl, *p_aoh, *p_aol,
                  *p_ffh, *p_ffl, *p_wbh, *p_wbl;
    cudaGetSymbolAddress((void**)&p_buf,  g_buf);
    cudaGetSymbolAddress((void**)&p_xh,   g_xh);
    cudaGetSymbolAddress((void**)&p_xl,   g_xl);
    cudaGetSymbolAddress((void**)&p_qkvh, g_qkvh);
    cudaGetSymbolAddress((void**)&p_qkvl, g_qkvl);
    cudaGetSymbolAddress((void**)&p_aoh,  g_aoh);
    cudaGetSymbolAddress((void**)&p_aol,  g_aol);
    cudaGetSymbolAddress((void**)&p_ffh,  g_ffh);
    cudaGetSymbolAddress((void**)&p_ffl,  g_ffl);
    cudaGetSymbolAddress((void**)&p_wbh,  g_wbh);
    cudaGetSymbolAddress((void**)&p_wbl,  g_wbl);

    cudaFuncSetAttribute(k_gemm,   cudaFuncAttributeMaxDynamicSharedMemorySize, SMEM_BYTES);
    cudaFuncSetAttribute(k_scores, cudaFuncAttributeMaxDynamicSharedMemorySize, SMEM_BYTES);
    cudaFuncSetAttribute(k_av,     cudaFuncAttributeMaxDynamicSharedMemorySize, SMEM_BYTES);
    cudaFuncSetAttribute(k_moe1,   cudaFuncAttributeMaxDynamicSharedMemorySize, SMEM_BYTES);
    cudaFuncSetAttribute(k_moe2,   cudaFuncAttributeMaxDynamicSharedMemorySize, SMEM_BYTES);

    k_embed<<<(TT * HH) / 256, 256>>>(ids, embed);

    for (int l = 0; l < LL; l++) {
        // QKV (qkv_w [3H][H] is already [n][k])
        k_conv_rm<<<3 * HH * HH / 1024, 256>>>(qkv_w + (long)l * 3 * HH * HH, p_wbh, p_wbl);
        k_gemm<<<dim3(3 * HH / TN, TT / TM), 256, SMEM_BYTES>>>(
            p_xh, p_xl, HH, p_wbh, p_wbl, HH, qkv_b + (long)l * 3 * HH,
            nullptr, p_qkvh, p_qkvl, 3 * HH, TT, 3 * HH, HH, 1.0f, 0);

        // attention
        k_scores<<<dim3(SS / TN, SS / TM, BB * NHD), 256, SMEM_BYTES>>>();
        k_softmax<<<BB * NHD * SS, 256>>>();
        k_conv_vt<<<dim3(HD / 32, SS / 32, BB * NHD), 256>>>();
        k_av<<<dim3(HD / TN, SS / TM, BB * NHD), 256, SMEM_BYTES>>>();

        // out proj (out_w [H][H] is [n][k])
        k_conv_rm<<<HH * HH / 1024, 256>>>(out_w + (long)l * HH * HH, p_wbh, p_wbl);
        k_gemm<<<dim3(HH / TN, TT / TM), 256, SMEM_BYTES>>>(
            p_aoh, p_aol, HH, p_wbh, p_wbl, HH, out_b + (long)l * HH,
            p_buf, nullptr, nullptr, HH, TT, HH, HH, 1.0f, 0);

        k_add_ln<<<TT, 256>>>(p_buf, ln1g + (long)l * HH, ln1b + (long)l * HH);

        // FFN
        k_conv_tr<<<dim3(FF4 / 32, HH / 32, 1), 256>>>(ffw1 + (long)l * HH * FF4, HH, FF4, p_wbh, p_wbl);
        k_gemm<<<dim3(FF4 / TN, TT / TM), 256, SMEM_BYTES>>>(
            p_xh, p_xl, HH, p_wbh, p_wbl, HH, ffb1 + (long)l * FF4,
            nullptr, p_ffh, p_ffl, FF4, TT, FF4, HH, 1.0f, 2);
        k_conv_tr<<<dim3(HH / 32, FF4 / 32, 1), 256>>>(ffw2 + (long)l * FF4 * HH, FF4, HH, p_wbh, p_wbl);
        k_gemm<<<dim3(HH / TN, TT / TM), 256, SMEM_BYTES>>>(
            p_ffh, p_ffl, FF4, p_wbh, p_wbl, FF4, ffb2 + (long)l * HH,
            p_buf, nullptr, nullptr, HH, TT, HH, FF4, 1.0f, 0);

        k_add_ln<<<TT, 256>>>(p_buf, ln2g + (long)l * HH, ln2b + (long)l * HH);

        // MoE
        k_zero_counts<<<1, 32>>>();
        k_gate<<<TT, 256>>>(gw + (long)l * HH * EE, gb + (long)l * EE);
        k_conv_tr<<<dim3(EH / 32, HH / 32, EE), 256>>>(ew1 + (long)l * EE * HH * EH, HH, EH, p_wbh, p_wbl);
        k_moe1<<<dim3(EH / TN, TT / TM, EE), 256, SMEM_BYTES>>>(eb1 + (long)l * EE * EH);
        k_conv_tr<<<dim3(HH / 32, EH / 32, EE), 256>>>(ew2 + (long)l * EE * EH * HH, EH, HH, p_wbh, p_wbl);
        k_moe2<<<dim3(HH / TN, TT / TM, EE), 256, SMEM_BYTES>>>(eb2 + (long)l * EE * HH);
        k_combine<<<(TT * HH) / 256, 256>>>();
    }

    // lm head: bf16x3 (error ~1e-5, replaces the tf32 4e-4 term)
    k_conv_tr<<<dim3(VV / 32, HH / 32, 1), 256>>>(lmw, HH, VV, p_wbh, p_wbl);
    k_gemm<<<dim3(VV / TN, TT / TM), 256, SMEM_BYTES>>>(
        p_xh, p_xl, HH, p_wbh, p_wbl, HH, lmb,
        out, nullptr, nullptr, VV, TT, VV, HH, 1.0f, 0);
}

// round 17
// speedup vs baseline: 2.8012x; 1.0289x over previous
#include <cuda_runtime.h>
#include <cuda_bf16.h>
#include <math.h>
#include <stdint.h>

// ---------------- problem constants ----------------
#define BB   4
#define SS   1024
#define TT   4096        // B*S tokens
#define HH   1024
#define NHD  4           // heads
#define HD   256         // head dim
#define EE   8           // experts
#define KK   2           // top-k
#define VV   32000
#define LL   2
#define FF4  4096        // 4H
#define EH   2048        // 2H

// ---------------- device scratch (no allocations allowed) ----------------
// fp32
__device__ float g_x[(size_t)TT * HH];
__device__ float g_scores[(size_t)BB * NHD * SS * SS];
__device__ float g_buf[(size_t)TT * HH];
__device__ float g_y[(size_t)TT * KK * HH];
__device__ int   g_list[EE * TT];
__device__ int   g_counts[EE];
// bf16 hi/lo planes
__device__ __nv_bfloat16 g_xh[(size_t)TT * HH],        g_xl[(size_t)TT * HH];
__device__ __nv_bfloat16 g_qkvh[(size_t)TT * 3 * HH],  g_qkvl[(size_t)TT * 3 * HH];
__device__ __nv_bfloat16 g_sph[(size_t)BB * NHD * SS * SS], g_spl[(size_t)BB * NHD * SS * SS];
__device__ __nv_bfloat16 g_vth[(size_t)BB * NHD * HD * SS], g_vtl[(size_t)BB * NHD * HD * SS];
__device__ __nv_bfloat16 g_aoh[(size_t)TT * HH],       g_aol[(size_t)TT * HH];
__device__ __nv_bfloat16 g_ffh[(size_t)TT * FF4],      g_ffl[(size_t)TT * FF4];
__device__ __nv_bfloat16 g_hh[(size_t)TT * KK * EH],   g_hl[(size_t)TT * KK * EH];
__device__ __nv_bfloat16 g_wbh[(size_t)VV * HH + 1024], g_wbl[(size_t)VV * HH + 1024];

// ---------------- helpers ----------------
__device__ __forceinline__ float gelu_exact(float v) {
    return 0.5f * v * (1.0f + erff(v * 0.70710678118654752440f));
}

__device__ __forceinline__ void split1(float v, __nv_bfloat16& h, __nv_bfloat16& l) {
    h = __float2bfloat16_rn(v);
    l = __float2bfloat16_rn(v - __bfloat162float(h));
}

__device__ __forceinline__ void split_pack(float v0, float v1, uint32_t& h, uint32_t& l) {
    __nv_bfloat16 h0, l0, h1, l1;
    split1(v0, h0, l0);
    split1(v1, h1, l1);
    h = (uint32_t)__bfloat16_as_ushort(h0) | ((uint32_t)__bfloat16_as_ushort(h1) << 16);
    l = (uint32_t)__bfloat16_as_ushort(l0) | ((uint32_t)__bfloat16_as_ushort(l1) << 16);
}

__device__ __forceinline__ void mma_bf16(float* d, const uint32_t* a, const uint32_t* b) {
    asm volatile(
        "mma.sync.aligned.m16n8k16.row.col.f32.bf16.bf16.f32 "
        "{%0,%1,%2,%3}, {%4,%5,%6,%7}, {%8,%9}, {%0,%1,%2,%3};"
        : "+f"(d[0]), "+f"(d[1]), "+f"(d[2]), "+f"(d[3])
        : "r"(a[0]), "r"(a[1]), "r"(a[2]), "r"(a[3]), "r"(b[0]), "r"(b[1]));
}

__device__ __forceinline__ uint32_t s2u(const void* p) {
    uint32_t a;
    asm("{ .reg .u64 t; cvta.to.shared.u64 t, %1; cvt.u32.u64 %0, t; }"
        : "=r"(a) : "l"(p));
    return a;
}

__device__ __forceinline__ void cpa16(uint32_t dst, const void* src) {
    asm volatile("cp.async.cg.shared.global [%0], [%1], 16;" :: "r"(dst), "l"(src));
}
#define CP_COMMIT() asm volatile("cp.async.commit_group;" ::: "memory")
#define CP_WAIT(n)  asm volatile("cp.async.wait_group %0;" :: "n"(n) : "memory")

__device__ __forceinline__ void ldsm4(uint32_t* r, uint32_t a) {
    asm volatile("ldmatrix.sync.aligned.m8n8.x4.shared.b16 {%0,%1,%2,%3}, [%4];"
        : "=r"(r[0]), "=r"(r[1]), "=r"(r[2]), "=r"(r[3]) : "r"(a));
}

// ================= bf16x3 GEMM engine: 128x256 tile, k64 stages, 512 thr =====
// C[m,n] = act( alpha * sum_k A[m,k]*B[n,k] + bias[n] )
// A: hi/lo bf16 planes, row stride lda. B: hi/lo planes [N][K], stride ldb.
// Outputs: Cf (fp32) and/or Ch/Cl (bf16 planes), row stride ldc.
// amap/amode row gather (0 direct, 1 amap[r]>>1, 2 amap[r]); cmap row scatter.
// Requirements: K%128==0, N%256==0, all strides even.
#define TM 128
#define TN 256
#define TK 64
#define NTHR 512
#define SA_H 0
#define SA_L 16384
#define SB_H 32768
#define SB_L 65536
#define STAGE_BYTES 98304
#define SMEM_BYTES  196608

__device__ void gemm5(
    const __nv_bfloat16* __restrict__ Ah, const __nv_bfloat16* __restrict__ Al, int lda,
    const __nv_bfloat16* __restrict__ Bh, const __nv_bfloat16* __restrict__ Bl, int ldb,
    const float* __restrict__ bias,
    float* __restrict__ Cf, __nv_bfloat16* __restrict__ Ch, __nv_bfloat16* __restrict__ Cl,
    int ldc, int M, int N, int K, float alpha, int act,
    const int* __restrict__ amap, int amode, const int* __restrict__ cmap)
{
    extern __shared__ char smem[];
    const uint32_t sb = s2u(smem);
    const int tid  = threadIdx.x;
    const int lane = tid & 31, warp = tid >> 5;
    const int wm = warp >> 2, wn = warp & 3;      // 4x4 warp grid: m32 x n64 each
    const int row0 = blockIdx.y * TM, col0 = blockIdx.x * TN;

    // cp.async descriptors: A 2 chunks, B 4 chunks (each chunk = 16B = 8 bf16)
    long a_src[2];
    uint32_t a_dst[2];
#pragma unroll
    for (int i = 0; i < 2; i++) {
        int lin = tid + i * NTHR;          // 0..1023
        int r = lin >> 3, c = lin & 7;
        int rg = row0 + r; if (rg > M - 1) rg = M - 1;
        long rr = rg;
        if (amode == 1)      rr = amap[rg] >> 1;
        else if (amode == 2) rr = amap[rg];
        a_src[i] = rr * (long)lda + c * 8;
        a_dst[i] = (uint32_t)(r * 128 + ((c ^ (r & 7)) * 16));
    }
    long b_src[4];
    uint32_t b_dst[4];
#pragma unroll
    for (int i = 0; i < 4; i++) {
        int lin = tid + i * NTHR;          // 0..2047
        int r = lin >> 3, c = lin & 7;
        b_src[i] = (long)(col0 + r) * ldb + c * 8;
        b_dst[i] = (uint32_t)(r * 128 + ((c ^ (r & 7)) * 16));
    }

    float acc[2][8][4];
#pragma unroll
    for (int mt = 0; mt < 2; mt++)
#pragma unroll
        for (int nt = 0; nt < 8; nt++)
#pragma unroll
            for (int q = 0; q < 4; q++) acc[mt][nt][q] = 0.f;

    const int nst = K / TK;

#define ISSUE(bufbit, k0) do { \
        uint32_t _b = sb + (bufbit) * STAGE_BYTES; \
        _Pragma("unroll") \
        for (int i = 0; i < 2; i++) { \
            cpa16(_b + SA_H + a_dst[i], Ah + a_src[i] + (k0)); \
            cpa16(_b + SA_L + a_dst[i], Al + a_src[i] + (k0)); \
        } \
        _Pragma("unroll") \
        for (int i = 0; i < 4; i++) { \
            cpa16(_b + SB_H + b_dst[i], Bh + b_src[i] + (k0)); \
            cpa16(_b + SB_L + b_dst[i], Bl + b_src[i] + (k0)); \
        } \
        CP_COMMIT(); \
    } while (0)

    ISSUE(0, 0);
    ISSUE(1, TK);
    CP_WAIT(1);
    __syncthreads();

    const int arow = wm * 32 + (lane & 15);
    const int brow = wn * 64 + (lane & 15);
    const int ksel = lane >> 4;             // 0/1: k8 half selector

    for (int s = 0; s < nst; s++) {
        const uint32_t base = sb + (s & 1) * STAGE_BYTES;
#pragma unroll
        for (int ks = 0; ks < 4; ks++) {
            uint32_t ah[2][4], alr[2][4];
#pragma unroll
            for (int mt = 0; mt < 2; mt++) {
                int r = arow + mt * 16;
                uint32_t ad = base + SA_H + r * 128 + (((ks * 2 + ksel) ^ (r & 7)) * 16);
                ldsm4(ah[mt], ad);
                ldsm4(alr[mt], ad + (SA_L - SA_H));
            }
#pragma unroll
            for (int j = 0; j < 4; j++) {
                uint32_t bh4[4], bl4[4];
                int r = brow + j * 16;
                uint32_t bd = base + SB_H + r * 128 + (((ks * 2 + ksel) ^ (r & 7)) * 16);
                ldsm4(bh4, bd);
                ldsm4(bl4, bd + (SB_L - SB_H));
#pragma unroll
                for (int t = 0; t < 2; t++) {
                    int nt = j * 2 + t;
                    uint32_t bh2[2] = { bh4[t], bh4[t + 2] };
                    uint32_t bl2[2] = { bl4[t], bl4[t + 2] };
                    mma_bf16(acc[0][nt], ah[0], bh2);
                    mma_bf16(acc[1][nt], ah[1], bh2);
                    mma_bf16(acc[0][nt], ah[0], bl2);
                    mma_bf16(acc[1][nt], ah[1], bl2);
                    mma_bf16(acc[0][nt], alr[0], bh2);
                    mma_bf16(acc[1][nt], alr[1], bh2);
                }
            }
        }
        __syncthreads();
        if (s + 2 < nst) {
            ISSUE(s & 1, (s + 2) * TK);
            CP_WAIT(1);
            __syncthreads();
        } else if (s + 1 < nst) {
            CP_WAIT(0);
            __syncthreads();
        }
    }

    // ---- epilogue: fragment registers -> C ----
    const int gid = lane >> 2, ctg = lane & 3;
#pragma unroll
    for (int mt = 0; mt < 2; mt++) {
#pragma unroll
        for (int half = 0; half < 2; half++) {
            int rg = row0 + wm * 32 + mt * 16 + gid + half * 8;
            if (rg >= M) continue;
            long co = (long)(cmap ? cmap[rg] : rg) * (long)ldc;
#pragma unroll
            for (int nt = 0; nt < 8; nt++) {
                int c = col0 + wn * 64 + nt * 8 + ctg * 2;
                float v0 = acc[mt][nt][half * 2 + 0] * alpha;
                float v1 = acc[mt][nt][half * 2 + 1] * alpha;
                if (bias) { v0 += bias[c]; v1 += bias[c + 1]; }
                if (act == 1) {
                    v0 = fmaxf(v0, 0.f); v1 = fmaxf(v1, 0.f);
                } else if (act == 2) {
                    v0 = gelu_exact(v0); v1 = gelu_exact(v1);
                }
                if (Cf) *(float2*)(Cf + co + c) = make_float2(v0, v1);
                if (Ch) {
                    uint32_t hw, lw;
                    split_pack(v0, v1, hw, lw);
                    *(uint32_t*)(Ch + co + c) = hw;
                    *(uint32_t*)(Cl + co + c) = lw;
                }
            }
        }
    }
#undef ISSUE
}

// ---------------- GEMM wrappers ----------------
__global__ void __launch_bounds__(NTHR) k_gemm(
    const __nv_bfloat16* Ah, const __nv_bfloat16* Al, int lda,
    const __nv_bfloat16* Bh, const __nv_bfloat16* Bl, int ldb,
    const float* bias, float* Cf, __nv_bfloat16* Ch, __nv_bfloat16* Cl, int ldc,
    int M, int N, int K, float alpha, int act)
{
    gemm5(Ah, Al, lda, Bh, Bl, ldb, bias, Cf, Ch, Cl, ldc,
          M, N, K, alpha, act, nullptr, 0, nullptr);
}

__global__ void __launch_bounds__(NTHR) k_scores()
{
    int z = blockIdx.z, b = z >> 2, h = z & 3;
    long qo = (long)b * SS * 3 * HH + (long)h * HD;
    gemm5(g_qkvh + qo, g_qkvl + qo, 3 * HH,
          g_qkvh + qo + HH, g_qkvl + qo + HH, 3 * HH,
          nullptr, g_scores + (long)z * SS * SS, nullptr, nullptr, SS,
          SS, SS, HD, 0.0625f, 0, nullptr, 0, nullptr);
}

__global__ void __launch_bounds__(NTHR) k_av()
{
    int z = blockIdx.z, b = z >> 2, h = z & 3;
    long po = (long)z * SS * SS;
    long vo = (long)z * HD * SS;
    long ao = (long)b * SS * HH + (long)h * HD;
    gemm5(g_sph + po, g_spl + po, SS, g_vth + vo, g_vtl + vo, SS,
          nullptr, nullptr, g_aoh + ao, g_aol + ao, HH,
          SS, HD, SS, 1.0f, 0, nullptr, 0, nullptr);
}

__global__ void __launch_bounds__(NTHR) k_moe1(const float* __restrict__ eb1)
{
    int e = blockIdx.z;
    int cnt = g_counts[e];
    if ((int)blockIdx.y * TM >= cnt) return;
    gemm5(g_xh, g_xl, HH,
          g_wbh + (long)e * EH * HH, g_wbl + (long)e * EH * HH, HH,
          eb1 + e * EH, nullptr, g_hh, g_hl, EH,
          cnt, EH, HH, 1.0f, 1, g_list + e * TT, 1, g_list + e * TT);
}

__global__ void __launch_bounds__(NTHR) k_moe2(const float* __restrict__ eb2)
{
    int e = blockIdx.z;
    int cnt = g_counts[e];
    if ((int)blockIdx.y * TM >= cnt) return;
    gemm5(g_hh, g_hl, EH,
          g_wbh + (long)e * HH * EH, g_wbl + (long)e * HH * EH, EH,
          eb2 + e * HH, g_y, nullptr, nullptr, HH,
          cnt, HH, EH, 1.0f, 0, g_list + e * TT, 2, g_list + e * TT);
}

// ---------------- conversion kernels ----------------
__global__ void __launch_bounds__(256) k_conv_rm(const float* __restrict__ src,
                                                 __nv_bfloat16* __restrict__ dh,
                                                 __nv_bfloat16* __restrict__ dl)
{
    long i4 = ((long)blockIdx.x * 256 + threadIdx.x) * 4;
    float4 v = *(const float4*)(src + i4);
    uint32_t h0, l0, h1, l1;
    split_pack(v.x, v.y, h0, l0);
    split_pack(v.z, v.w, h1, l1);
    *(uint2*)(dh + i4) = make_uint2(h0, h1);
    *(uint2*)(dl + i4) = make_uint2(l0, l1);
}

__global__ void __launch_bounds__(256) k_conv_tr(const float* __restrict__ src, int R, int C,
                                                 __nv_bfloat16* __restrict__ dh,
                                                 __nv_bfloat16* __restrict__ dl)
{
    __shared__ float t[32][33];
    long zo = (long)blockIdx.z * R * C;
    int c0 = blockIdx.x * 32, r0 = blockIdx.y * 32;
    int tx = threadIdx.x & 31, ty = threadIdx.x >> 5;
#pragma unroll
    for (int j = 0; j < 4; j++)
        t[ty + j * 8][tx] = src[zo + (long)(r0 + ty + j * 8) * C + c0 + tx];
    __syncthreads();
#pragma unroll
    for (int j = 0; j < 4; j++) {
        float v = t[tx][ty + j * 8];
        __nv_bfloat16 h, l;
        split1(v, h, l);
        long o = zo + (long)(c0 + ty + j * 8) * R + r0 + tx;
        dh[o] = h; dl[o] = l;
    }
}

__global__ void __launch_bounds__(256) k_conv_vt()
{
    __shared__ __nv_bfloat16 th[32][34], tl[32][34];
    int z = blockIdx.z, b = z >> 2, h = z & 3;
    long sbase = (long)b * SS * 3 * HH + 2 * HH + (long)h * HD;
    long dbase = (long)z * HD * SS;
    int d0 = blockIdx.x * 32, s0 = blockIdx.y * 32;
    int tx = threadIdx.x & 31, ty = threadIdx.x >> 5;
#pragma unroll
    for (int j = 0; j < 4; j++) {
        long so = sbase + (long)(s0 + ty + j * 8) * (3 * HH) + d0 + tx;
        th[ty + j * 8][tx] = g_qkvh[so];
        tl[ty + j * 8][tx] = g_qkvl[so];
    }
    __syncthreads();
#pragma unroll
    for (int j = 0; j < 4; j++) {
        long o = dbase + (long)(d0 + ty + j * 8) * SS + s0 + tx;
        g_vth[o] = th[tx][ty + j * 8];
        g_vtl[o] = tl[tx][ty + j * 8];
    }
}

// ---------------- elementwise / reduction kernels ----------------
__global__ void __launch_bounds__(256) k_embed(const int* __restrict__ ids,
                                               const float* __restrict__ emb)
{
    long i = (long)blockIdx.x * 256 + threadIdx.x;
    int t = (int)(i >> 10);
    int h = (int)(i & 1023);
    float v = emb[(long)ids[t] * HH + h];
    g_x[i] = v;
    __nv_bfloat16 hb, lb;
    split1(v, hb, lb);
    g_xh[i] = hb; g_xl[i] = lb;
}

__global__ void __launch_bounds__(256) k_softmax()
{
    const long base = (long)blockIdx.x * SS;
    const float* row = g_scores + base;
    const int tid = threadIdx.x;
    __shared__ float red[256];

    float v[4];
#pragma unroll
    for (int i = 0; i < 4; i++) v[i] = row[tid + i * 256];

    float m = fmaxf(fmaxf(v[0], v[1]), fmaxf(v[2], v[3]));
    red[tid] = m; __syncthreads();
    for (int o = 128; o > 0; o >>= 1) {
        if (tid < o) red[tid] = fmaxf(red[tid], red[tid + o]);
        __syncthreads();
    }
    m = red[0];
    __syncthreads();

    float s = 0.f;
#pragma unroll
    for (int i = 0; i < 4; i++) { v[i] = expf(v[i] - m); s += v[i]; }
    red[tid] = s; __syncthreads();
    for (int o = 128; o > 0; o >>= 1) {
        if (tid < o) red[tid] += red[tid + o];
        __syncthreads();
    }
    const float inv = 1.f / red[0];
#pragma unroll
    for (int i = 0; i < 4; i++) {
        __nv_bfloat16 hb, lb;
        split1(v[i] * inv, hb, lb);
        g_sph[base + tid + i * 256] = hb;
        g_spl[base + tid + i * 256] = lb;
    }
}

__global__ void __launch_bounds__(256) k_add_ln(const float* __restrict__ res,
                                                const float* __restrict__ g,
                                                const float* __restrict__ b)
{
    const int t = blockIdx.x;
    const int tid = threadIdx.x;
    const long base = (long)t * HH;
    __shared__ float red[256];

    float v[4];
    float s = 0.f;
#pragma unroll
    for (int i = 0; i < 4; i++) {
        v[i] = g_x[base + tid + i * 256] + res[base + tid + i * 256];
        s += v[i];
    }
    red[tid] = s; __syncthreads();
    for (int o = 128; o > 0; o >>= 1) {
        if (tid < o) red[tid] += red[tid + o];
        __syncthreads();
    }
    const float mean = red[0] * (1.0f / HH);
    __syncthreads();

    float s2 = 0.f;
#pragma unroll
    for (int i = 0; i < 4; i++) {
        float d = v[i] - mean;
        s2 += d * d;
    }
    red[tid] = s2; __syncthreads();
    for (int o = 128; o > 0; o >>= 1) {
        if (tid < o) red[tid] += red[tid + o];
        __syncthreads();
    }
    const float inv = rsqrtf(red[0] * (1.0f / HH) + 1e-5f);
#pragma unroll
    for (int i = 0; i < 4; i++) {
        int c = tid + i * 256;
        float o = (v[i] - mean) * inv * g[c] + b[c];
        g_x[base + c] = o;
        __nv_bfloat16 hb, lb;
        split1(o, hb, lb);
        g_xh[base + c] = hb; g_xl[base + c] = lb;
    }
}

__global__ void k_zero_counts()
{
    if (threadIdx.x < EE) g_counts[threadIdx.x] = 0;
}

__global__ void __launch_bounds__(256) k_gate(const float* __restrict__ gw,
                                              const float* __restrict__ gb)
{
    const int t = blockIdx.x;
    const int tid = threadIdx.x;
    const int w = tid >> 5, lane = tid & 31;
    const float* xr = g_x + (long)t * HH;

    float s = 0.f;
    for (int j = lane; j < HH; j += 32) s += xr[j] * gw[(long)j * EE + w];
#pragma unroll
    for (int o = 16; o > 0; o >>= 1) s += __shfl_down_sync(0xFFFFFFFFu, s, o);

    __shared__ float lg[EE];
    if (lane == 0) lg[w] = s + gb[w];
    __syncthreads();

    if (tid == 0) {
        int i1 = 0;
        for (int e = 1; e < EE; e++) if (lg[e] > lg[i1]) i1 = e;
        int i2 = -1;
        for (int e = 0; e < EE; e++) {
            if (e == i1) continue;
            if (i2 < 0 || lg[e] > lg[i2]) i2 = e;
        }
        int p1 = atomicAdd(&g_counts[i1], 1);
        g_list[i1 * TT + p1] = t * 2 + 0;
        int p2 = atomicAdd(&g_counts[i2], 1);
        g_list[i2 * TT + p2] = t * 2 + 1;
    }
}

__global__ void __launch_bounds__(256) k_combine()
{
    long i = (long)blockIdx.x * 256 + threadIdx.x;
    int t = (int)(i >> 10);
    int h = (int)(i & 1023);
    float v = g_y[((long)t * 2) * HH + h] + g_y[((long)t * 2 + 1) * HH + h];
    g_x[i] = v;
    __nv_bfloat16 hb, lb;
    split1(v, hb, lb);
    g_xh[i] = hb; g_xl[i] = lb;
}

// ---------------- host launcher ----------------
extern "C" void kernel_launch(void* const* d_in, const int* in_sizes, int n_in,
                              void* d_out, int out_size)
{
    (void)in_sizes; (void)n_in; (void)out_size;

    const int*   ids    = (const int*)d_in[0];
    const float* embed  = (const float*)d_in[1];
    const float* qkv_w  = (const float*)d_in[2];
    const float* qkv_b  = (const float*)d_in[3];
    const float* out_w  = (const float*)d_in[4];
    const float* out_b  = (const float*)d_in[5];
    const float* ln1g   = (const float*)d_in[6];
    const float* ln1b   = (const float*)d_in[7];
    const float* ffw1   = (const float*)d_in[8];
    const float* ffb1   = (const float*)d_in[9];
    const float* ffw2   = (const float*)d_in[10];
    const float* ffb2   = (const float*)d_in[11];
    const float* ln2g   = (const float*)d_in[12];
    const float* ln2b   = (const float*)d_in[13];
    const float* gw     = (const float*)d_in[14];
    const float* gb     = (const float*)d_in[15];
    const float* ew1    = (const float*)d_in[16];
    const float* eb1    = (const float*)d_in[17];
    const float* ew2    = (const float*)d_in[18];
    const float* eb2    = (const float*)d_in[19];
    const float* lmw    = (const float*)d_in[20];
    const float* lmb    = (const float*)d_in[21];
    float* out = (float*)d_out;

    float *p_buf;
    __nv_bfloat16 *p_xh, *p_xl, *p_qkvh, *p_qkvl, *p_aoh, *p_aol,
                  *p_ffh, *p_ffl, *p_wbh, *p_wbl;
    cudaGetSymbolAddress((void**)&p_buf,  g_buf);
    cudaGetSymbolAddress((void**)&p_xh,   g_xh);
    cudaGetSymbolAddress((void**)&p_xl,   g_xl);
    cudaGetSymbolAddress((void**)&p_qkvh, g_qkvh);
    cudaGetSymbolAddress((void**)&p_qkvl, g_qkvl);
    cudaGetSymbolAddress((void**)&p_aoh,  g_aoh);
    cudaGetSymbolAddress((void**)&p_aol,  g_aol);
    cudaGetSymbolAddress((void**)&p_ffh,  g_ffh);
    cudaGetSymbolAddress((void**)&p_ffl,  g_ffl);
    cudaGetSymbolAddress((void**)&p_wbh,  g_wbh);
    cudaGetSymbolAddress((void**)&p_wbl,  g_wbl);

    cudaFuncSetAttribute(k_gemm,   cudaFuncAttributeMaxDynamicSharedMemorySize, SMEM_BYTES);
    cudaFuncSetAttribute(k_scores, cudaFuncAttributeMaxDynamicSharedMemorySize, SMEM_BYTES);
    cudaFuncSetAttribute(k_av,     cudaFuncAttributeMaxDynamicSharedMemorySize, SMEM_BYTES);
    cudaFuncSetAttribute(k_moe1,   cudaFuncAttributeMaxDynamicSharedMemorySize, SMEM_BYTES);
    cudaFuncSetAttribute(k_moe2,   cudaFuncAttributeMaxDynamicSharedMemorySize, SMEM_BYTES);

    k_embed<<<(TT * HH) / 256, 256>>>(ids, embed);

    for (int l = 0; l < LL; l++) {
        // QKV (qkv_w [3H][H] is already [n][k])
        k_conv_rm<<<3 * HH * HH / 1024, 256>>>(qkv_w + (long)l * 3 * HH * HH, p_wbh, p_wbl);
        k_gemm<<<dim3(3 * HH / TN, TT / TM), NTHR, SMEM_BYTES>>>(
            p_xh, p_xl, HH, p_wbh, p_wbl, HH, qkv_b + (long)l * 3 * HH,
            nullptr, p_qkvh, p_qkvl, 3 * HH, TT, 3 * HH, HH, 1.0f, 0);

        // attention
        k_scores<<<dim3(SS / TN, SS / TM, BB * NHD), NTHR, SMEM_BYTES>>>();
        k_softmax<<<BB * NHD * SS, 256>>>();
        k_conv_vt<<<dim3(HD / 32, SS / 32, BB * NHD), 256>>>();
        k_av<<<dim3(HD / TN, SS / TM, BB * NHD), NTHR, SMEM_BYTES>>>();

        // out proj (out_w [H][H] is [n][k])
        k_conv_rm<<<HH * HH / 1024, 256>>>(out_w + (long)l * HH * HH, p_wbh, p_wbl);
        k_gemm<<<dim3(HH / TN, TT / TM), NTHR, SMEM_BYTES>>>(
            p_aoh, p_aol, HH, p_wbh, p_wbl, HH, out_b + (long)l * HH,
            p_buf, nullptr, nullptr, HH, TT, HH, HH, 1.0f, 0);

        k_add_ln<<<TT, 256>>>(p_buf, ln1g + (long)l * HH, ln1b + (long)l * HH);

        // FFN
        k_conv_tr<<<dim3(FF4 / 32, HH / 32, 1), 256>>>(ffw1 + (long)l * HH * FF4, HH, FF4, p_wbh, p_wbl);
        k_gemm<<<dim3(FF4 / TN, TT / TM), NTHR, SMEM_BYTES>>>(
            p_xh, p_xl, HH, p_wbh, p_wbl, HH, ffb1 + (long)l * FF4,
            nullptr, p_ffh, p_ffl, FF4, TT, FF4, HH, 1.0f, 2);
        k_conv_tr<<<dim3(HH / 32, FF4 / 32, 1), 256>>>(ffw2 + (long)l * FF4 * HH, FF4, HH, p_wbh, p_wbl);
        k_gemm<<<dim3(HH / TN, TT / TM), NTHR, SMEM_BYTES>>>(
            p_ffh, p_ffl, FF4, p_wbh, p_wbl, FF4, ffb2 + (long)l * HH,
            p_buf, nullptr, nullptr, HH, TT, HH, FF4, 1.0f, 0);

        k_add_ln<<<TT, 256>>>(p_buf, ln2g + (long)l * HH, ln2b + (long)l * HH);

        // MoE
        k_zero_counts<<<1, 32>>>();
        k_gate<<<TT, 256>>>(gw + (long)l * HH * EE, gb + (long)l * EE);
        k_conv_tr<<<dim3(EH / 32, HH / 32, EE), 256>>>(ew1 + (long)l * EE * HH * EH, HH, EH, p_wbh, p_wbl);
        k_moe1<<<dim3(EH / TN, TT / TM, EE), NTHR, SMEM_BYTES>>>(eb1 + (long)l * EE * EH);
        k_conv_tr<<<dim3(HH / 32, EH / 32, EE), 256>>>(ew2 + (long)l * EE * EH * HH, EH, HH, p_wbh, p_wbl);
        k_moe2<<<dim3(HH / TN, TT / TM, EE), NTHR, SMEM_BYTES>>>(eb2 + (long)l * EE * HH);
        k_combine<<<(TT * HH) / 256, 256>>>();
    }

    // lm head: bf16x3
    k_conv_tr<<<dim3(VV / 32, HH / 32, 1), 256>>>(lmw, HH, VV, p_wbh, p_wbl);
    k_gemm<<<dim3(VV / TN, TT / TM), NTHR, SMEM_BYTES>>>(
        p_xh, p_xl, HH, p_wbh, p_wbl, HH, lmb,
        out, nullptr, nullptr, VV, TT, VV, HH, 1.0f, 0);
}